// round 14
// baseline (speedup 1.0000x reference)
#include <cuda_runtime.h>
#include <cuda_bf16.h>
#include <cuda_fp16.h>
#include <math.h>
#include <stdint.h>

#define B_   512
#define T_   1005
#define E_   100
#define L_   10
#define N_   20
#define V_   32000
#define NCH  100      // n_full = T/L
#define REST 5        // T % L

// ---- scratch (no allocations allowed) ----
__device__ float g_ya[B_ * E_];                 // prelu(y)
__device__ uint32_t g_Rhi[V_ * 60];             // R_w bf16-hi pairs, 240B rows
__device__ uint32_t g_Rlo[V_ * 60];
__device__ uint32_t g_Yhi[B_ * 60];             // ya bf16-hi pairs
__device__ uint32_t g_Ylo[B_ * 60];

// ---- warp MMA helpers (portable PTX, sm_80+) ----
__device__ __forceinline__ uint32_t smem_u32(const void* p) {
    uint32_t a;
    asm("{ .reg .u64 t; cvta.to.shared.u64 t, %1; cvt.u32.u64 %0, t; }"
        : "=r"(a) : "l"(p));
    return a;
}
__device__ __forceinline__ void ldsm4(uint32_t* r, uint32_t a) {
    asm volatile("ldmatrix.sync.aligned.m8n8.x4.shared.b16 {%0,%1,%2,%3}, [%4];"
        : "=r"(r[0]), "=r"(r[1]), "=r"(r[2]), "=r"(r[3]) : "r"(a));
}
__device__ __forceinline__ void ldsm2(uint32_t* r, uint32_t a) {
    asm volatile("ldmatrix.sync.aligned.m8n8.x2.shared.b16 {%0,%1}, [%2];"
        : "=r"(r[0]), "=r"(r[1]) : "r"(a));
}
// bf16 MMA (out GEMM)
__device__ __forceinline__ void mma16816(float* c, const uint32_t* a, const uint32_t* b) {
    asm volatile(
        "mma.sync.aligned.m16n8k16.row.col.f32.bf16.bf16.f32 "
        "{%0,%1,%2,%3}, {%4,%5,%6,%7}, {%8,%9}, {%0,%1,%2,%3};"
        : "+f"(c[0]), "+f"(c[1]), "+f"(c[2]), "+f"(c[3])
        : "r"(a[0]), "r"(a[1]), "r"(a[2]), "r"(a[3]), "r"(b[0]), "r"(b[1]));
}
// fp16 MMA (scan GEMM)
__device__ __forceinline__ void mma16816h(float* c, const uint32_t* a, const uint32_t* b) {
    asm volatile(
        "mma.sync.aligned.m16n8k16.row.col.f32.f16.f16.f32 "
        "{%0,%1,%2,%3}, {%4,%5,%6,%7}, {%8,%9}, {%0,%1,%2,%3};"
        : "+f"(c[0]), "+f"(c[1]), "+f"(c[2]), "+f"(c[3])
        : "r"(a[0]), "r"(a[1]), "r"(a[2]), "r"(a[3]), "r"(b[0]), "r"(b[1]));
}
// split two fp32 into packed bf16 hi + residual lo (out GEMM convert)
__device__ __forceinline__ void split2(float x0, float x1, uint32_t& hi, uint32_t& lo) {
    __nv_bfloat162 bh = __floats2bfloat162_rn(x0, x1);
    uint32_t h = *reinterpret_cast<uint32_t*>(&bh);
    float hf0 = __uint_as_float(h << 16);
    float hf1 = __uint_as_float(h & 0xffff0000u);
    __nv_bfloat162 bl = __floats2bfloat162_rn(x0 - hf0, x1 - hf1);
    hi = h;
    lo = *reinterpret_cast<uint32_t*>(&bl);
}
// pack two fp32 into fp16x2
__device__ __forceinline__ uint32_t pack_h2(float x0, float x1) {
    __half2 h2 = __floats2half2_rn(x0, x1);
    return *reinterpret_cast<uint32_t*>(&h2);
}

// ============================================================
// K2: persistent scan on warp MMA (fp16 HMMA), 2 CTAs/SM.
//     256 CTAs x 2 batches; 6 MMA warps (M=48 pad) + 2 helpers.
// ============================================================
#define NB   2
#define NTH  256
#define BST  240
#define HST  108
#define SST  104
#define NROW 40       // NB * N_

#define OFF_AHI 0                          // 48*240 = 11520
#define OFF_BHI 11520                      // 112*240 = 26880 -> 38400
#define OFF_H   38400                      // 40*108*4 = 17280 -> 55680
#define OFF_W2  55680                      // 100*50*4 = 20000 -> 75680 (W fp16 pairs)
#define OFF_WM  75680                      // 8320 -> 84000
#define OFF_VW  84000                      // 8320 -> 92320
#define OFF_S   92320                      // 2*2*104*4 = 1664 -> 93984
#define OFF_SSW 93984                      // 832 -> 94816
#define OFF_G   94816                      // 160 -> 94976
#define OFF_GP  94976                      // 320 -> 95296
#define OFF_F   95296                      // 4000 -> 99296
#define SCAN_SMEM 99296

__global__ __launch_bounds__(NTH, 2) void scan_mma_kernel(
    const float* __restrict__ U_w, const float* __restrict__ V_w,
    const float* __restrict__ W_w, const float* __restrict__ w_mem,
    const float* __restrict__ h0,  const float* __restrict__ a_dm_p,
    const float* __restrict__ in_data, const float* __restrict__ f_w,
    const float* __restrict__ H_w, const float* __restrict__ H_b,
    const float* __restrict__ a_out_p)
{
    extern __shared__ char smc[];
    float* sH  = (float*)(smc + OFF_H);
    uint32_t* sW2 = (uint32_t*)(smc + OFF_W2);
    float* sWm = (float*)(smc + OFF_WM);
    float* sVw = (float*)(smc + OFF_VW);
    float* sS  = (float*)(smc + OFF_S);
    float* sSW = (float*)(smc + OFF_SSW);
    float* sG  = (float*)(smc + OFF_G);
    float* sGp = (float*)(smc + OFF_GP);
    float* sF  = (float*)(smc + OFF_F);

    const int tid = threadIdx.x;
    const int w = tid >> 5;
    const int lane = tid & 31;
    const int b0g = blockIdx.x * NB;
    const float adm = *a_dm_p;
    const uint32_t smb = smem_u32(smc);

    // ---- zero A+B tiles (pad rows/cols must stay zero) ----
    for (int i = tid; i < OFF_H / 4; i += NTH) ((uint32_t*)smc)[i] = 0;
    __syncthreads();

    // ---- stage U (fp16), W (fp16 pairs), w_mem, f, h init + A tile ----
    for (int i = tid; i < E_ * 50; i += NTH) {
        int f_ = i / 50, p = i % 50;
        float2 uv = *(const float2*)(U_w + f_ * E_ + 2 * p);
        *(uint32_t*)(smc + OFF_BHI + f_ * BST + p * 4) = pack_h2(uv.x, uv.y);
    }
    for (int i = tid; i < E_ * 50; i += NTH) {
        int f_ = i / 50, p = i % 50;
        float2 wv = *(const float2*)(W_w + f_ * E_ + 2 * p);
        sW2[f_ * 50 + p] = pack_h2(wv.x, wv.y);
    }
    for (int i = tid; i < L_ * E_; i += NTH) sF[i] = f_w[i];
    for (int i = tid; i < N_ * E_; i += NTH) {
        int n_ = i / E_, e_ = i % E_;
        sWm[n_ * SST + e_] = w_mem[i];
    }
    for (int i = tid; i < NROW * 50; i += NTH) {
        int row = i / 50, p = i % 50;
        float2 hv = *(const float2*)(h0 + (row % N_) * E_ + 2 * p);
        *(float2*)(sH + row * HST + 2 * p) = hv;
        *(uint32_t*)(smc + OFF_AHI + row * BST + p * 4) = pack_h2(hv.x, hv.y);
    }
    if (tid < 2 * NROW) { sGp[tid] = (tid & 1) ? 0.f : 1.f; }
    __syncthreads();
    // Vw[n][f] = w_mem[n] . V_w[f] (one-time)
    for (int i = tid; i < N_ * E_; i += NTH) {
        int n_ = i / E_, f_ = i % E_;
        float acc = 0.f;
        for (int e_ = 0; e_ < E_; e_++) acc += sWm[n_ * SST + e_] * V_w[f_ * E_ + e_];
        sVw[n_ * SST + f_] = acc;
    }
    // s_0 = infos(t=0)
    for (int i = tid; i < NB * E_; i += NTH) {
        int bi = i / E_, e_ = i % E_;
        const float* ip = in_data + (long)(b0g + bi) * T_ * E_ + e_;
        float acc = 0.f;
#pragma unroll
        for (int l = 0; l < L_; l++) acc += sF[l * E_ + e_] * ip[(long)l * E_];
        sS[bi * SST + e_] = acc;
    }
    __syncthreads();

    const int stripe = w >> 1, nh = w & 1;
    const int m0 = stripe * 16;
    const int qr = lane >> 2, qc = lane & 3;
    const int r0 = m0 + qr, r1 = r0 + 8;
    const bool val1 = (r1 < NROW);           // stripe 2 upper half is pad
    const int grp = lane >> 3, lr = lane & 7;

    const int hid = tid - 192;               // helper index 0..63 (w>=6)
    const bool h3 = (hid >= 0) && (hid < NB * E_ - 192);

    for (int t = 0; t < NCH; t++) {
        const float* sScur = sS + (t & 1) * NB * SST;

        float acc[7][4];
        float inv0 = 0.f, inv1 = 1.f;
        float v0[10], v1[10], v2[10], v3[10];

        // ================= phase A: fp16 MMA | helpers ====================
        if (w < 6) {
            inv0 = rsqrtf(sGp[2 * r0] + sGp[2 * r0 + 1]);
            if (val1) inv1 = rsqrtf(sGp[2 * r1] + sGp[2 * r1 + 1]);
#pragma unroll
            for (int j = 0; j < 7; j++)
#pragma unroll
                for (int q = 0; q < 4; q++) acc[j][q] = 0.f;
            const uint32_t aBase = smb + OFF_AHI;
            const uint32_t bhBase = smb + OFF_BHI;
#pragma unroll
            for (int k = 0; k < 7; k++) {
                uint32_t ah[4];
                uint32_t aaddr = aBase + (uint32_t)((m0 + lr + ((grp & 1) << 3)) * BST
                               + k * 32 + ((grp >> 1) << 4));
                ldsm4(ah, aaddr);
                uint32_t bh[14];
#pragma unroll
                for (int pq = 0; pq < 3; pq++) {
                    int t0 = nh * 7 + pq * 2;
                    uint32_t addr = bhBase + (uint32_t)((t0 * 8 + lr + (grp >> 1) * 8) * BST
                                  + k * 32 + (grp & 1) * 16);
                    ldsm4(&bh[pq * 4], addr);
                }
#pragma unroll
                for (int j = 0; j < 6; j++) {
                    mma16816h(acc[j], ah, &bh[2 * j]);
                }
                if (nh == 0) {   // tail tile j=6 (cols 48-55)
                    uint32_t addr = bhBase + (uint32_t)((6 * 8 + lr) * BST
                                  + k * 32 + ((lane >> 3) & 1) * 16);
                    uint32_t bht[2];
                    ldsm2(bht, addr);
                    mma16816h(acc[6], ah, bht);
                }
            }
        } else {
            // ---- early-issue LDGs for s_{t+1} ----
            if (t + 1 < NCH) {
                {
                    int bi = hid / E_, e = hid % E_;
                    const float* ip = in_data + ((long)(b0g + bi) * T_ + (t + 1) * L_) * E_ + e;
#pragma unroll
                    for (int l = 0; l < L_; l++) v0[l] = ip[(long)l * E_];
                }
                {
                    int i = hid + 64;
                    int bi = i / E_, e = i % E_;
                    const float* ip = in_data + ((long)(b0g + bi) * T_ + (t + 1) * L_) * E_ + e;
#pragma unroll
                    for (int l = 0; l < L_; l++) v1[l] = ip[(long)l * E_];
                }
                {
                    int i = hid + 128;
                    int bi = i / E_, e = i % E_;
                    const float* ip = in_data + ((long)(b0g + bi) * T_ + (t + 1) * L_) * E_ + e;
#pragma unroll
                    for (int l = 0; l < L_; l++) v2[l] = ip[(long)l * E_];
                }
                if (h3) {
                    int i = hid + 192;
                    int bi = i / E_, e = i % E_;
                    const float* ip = in_data + ((long)(b0g + bi) * T_ + (t + 1) * L_) * E_ + e;
#pragma unroll
                    for (int l = 0; l < L_; l++) v3[l] = ip[(long)l * E_];
                }
            }
            // ---- sSW for f = hid and f = hid+64 (W fp16 pairs) ----
#pragma unroll 1
            for (int ff = 0; ff < 2; ff++) {
                int f_ = hid + ff * 64;
                if (f_ < E_) {
                    float a0 = 0.f, a1 = 0.f;
                    const uint32_t* wp = sW2 + f_ * 50;
                    const float* sp0 = sScur;
                    const float* sp1 = sScur + SST;
                    for (int p = 0; p < 50; p++) {
                        uint32_t wu = wp[p];
                        __half2 wh = *reinterpret_cast<__half2*>(&wu);
                        float2 wf = __half22float2(wh);
                        float2 s0 = *(const float2*)(sp0 + 2 * p);
                        float2 s1 = *(const float2*)(sp1 + 2 * p);
                        a0 += wf.x * s0.x + wf.y * s0.y;
                        a1 += wf.x * s1.x + wf.y * s1.y;
                    }
                    sSW[0 * SST + f_] = a0;
                    sSW[1 * SST + f_] = a1;
                }
            }
            // ---- gate for row = hid ----
            if (hid < NROW) {
                int row = hid;
                int bi = row / N_, ne = row % N_;
                const float* hp = sH + row * HST;
                const float* wp = sWm + ne * SST;
                const float* sp = sScur + bi * SST;
                float hs = 0.f, ws = 0.f;
                for (int e4 = 0; e4 < 25; e4++) {
                    float4 hv = *(const float4*)(hp + e4 * 4);
                    float4 wv = *(const float4*)(wp + e4 * 4);
                    float4 sv = *(const float4*)(sp + e4 * 4);
                    hs += hv.x * sv.x + hv.y * sv.y + hv.z * sv.z + hv.w * sv.w;
                    ws += wv.x * sv.x + wv.y * sv.y + wv.z * sv.z + wv.w * sv.w;
                }
                float inv = rsqrtf(sGp[2 * row] + sGp[2 * row + 1]);
                sG[row] = 1.f / (1.f + expf(-(inv * hs + ws)));
            }
        }
        __syncthreads();

        // ================= phase B: epilogue + A-tile store ===============
        if (w < 6) {
            float g0 = sG[r0];
            float g1 = val1 ? sG[r1] : 0.f;
            int bi0 = r0 / N_, ne0 = r0 % N_;
            int bi1 = val1 ? (r1 / N_) : 0, ne1 = val1 ? (r1 % N_) : 0;
            float ssq0 = 0.f, ssq1 = 0.f;
#pragma unroll
            for (int j = 0; j < 7; j++) {
                int f0 = (nh * 7 + j) * 8 + 2 * qc;
                if (f0 < 100) {
                    float2 vw0 = *(const float2*)(sVw + ne0 * SST + f0);
                    float2 sw0 = *(const float2*)(sSW + bi0 * SST + f0);
                    float2 hv0 = *(const float2*)(sH + r0 * HST + f0);
                    float c0 = acc[j][0] * inv0 + vw0.x + sw0.x;
                    float c1 = acc[j][1] * inv0 + vw0.y + sw0.y;
                    c0 = (c0 >= 0.f) ? c0 : adm * c0;
                    c1 = (c1 >= 0.f) ? c1 : adm * c1;
                    float n0v = hv0.x * inv0 + g0 * c0;
                    float n1v = hv0.y * inv0 + g0 * c1;
                    *(float2*)(sH + r0 * HST + f0) = make_float2(n0v, n1v);
                    ssq0 += n0v * n0v + n1v * n1v;
                    *(uint32_t*)(smc + OFF_AHI + r0 * BST + f0 * 2) = pack_h2(n0v, n1v);

                    if (val1) {
                        float2 vw1 = *(const float2*)(sVw + ne1 * SST + f0);
                        float2 sw1 = *(const float2*)(sSW + bi1 * SST + f0);
                        float2 hv1 = *(const float2*)(sH + r1 * HST + f0);
                        float d0 = acc[j][2] * inv1 + vw1.x + sw1.x;
                        float d1 = acc[j][3] * inv1 + vw1.y + sw1.y;
                        d0 = (d0 >= 0.f) ? d0 : adm * d0;
                        d1 = (d1 >= 0.f) ? d1 : adm * d1;
                        float m0v = hv1.x * inv1 + g1 * d0;
                        float m1v = hv1.y * inv1 + g1 * d1;
                        *(float2*)(sH + r1 * HST + f0) = make_float2(m0v, m1v);
                        ssq1 += m0v * m0v + m1v * m1v;
                        *(uint32_t*)(smc + OFF_AHI + r1 * BST + f0 * 2) = pack_h2(m0v, m1v);
                    }
                }
            }
            ssq0 += __shfl_xor_sync(0xffffffffu, ssq0, 1);
            ssq0 += __shfl_xor_sync(0xffffffffu, ssq0, 2);
            ssq1 += __shfl_xor_sync(0xffffffffu, ssq1, 1);
            ssq1 += __shfl_xor_sync(0xffffffffu, ssq1, 2);
            if (qc == 0) {
                sGp[2 * r0 + nh] = ssq0;
                if (val1) sGp[2 * r1 + nh] = ssq1;
            }
        } else if (t + 1 < NCH) {
            float* sNxt = sS + ((t + 1) & 1) * NB * SST;
            {
                int bi = hid / E_, e = hid % E_;
                float a = 0.f;
#pragma unroll
                for (int l = 0; l < L_; l++) a += sF[l * E_ + e] * v0[l];
                sNxt[bi * SST + e] = a;
            }
            {
                int i = hid + 64;
                int bi = i / E_, e = i % E_;
                float a = 0.f;
#pragma unroll
                for (int l = 0; l < L_; l++) a += sF[l * E_ + e] * v1[l];
                sNxt[bi * SST + e] = a;
            }
            {
                int i = hid + 128;
                int bi = i / E_, e = i % E_;
                float a = 0.f;
#pragma unroll
                for (int l = 0; l < L_; l++) a += sF[l * E_ + e] * v2[l];
                sNxt[bi * SST + e] = a;
            }
            if (h3) {
                int i = hid + 192;
                int bi = i / E_, e = i % E_;
                float a = 0.f;
#pragma unroll
                for (int l = 0; l < L_; l++) a += sF[l * E_ + e] * v3[l];
                sNxt[bi * SST + e] = a;
            }
        }
        __syncthreads();
    }

    // ================= fused attention + head ==========================
    if (tid < NROW) sG[tid] = rsqrtf(sGp[2 * tid] + sGp[2 * tid + 1]);
    __syncthreads();
    for (int i = tid; i < NROW * E_; i += NTH) {
        int row = i / E_, e_ = i % E_;
        sH[row * HST + e_] *= sG[row];
    }
    {
        float* sQ = sS;
        for (int i = tid; i < NB * E_; i += NTH) {
            int bi = i / E_, e_ = i % E_;
            const float* ip = in_data + ((long)(b0g + bi) * T_ + NCH * L_) * E_ + e_;
            float acc = 0.f;
#pragma unroll
            for (int l = 0; l < REST; l++) acc += sF[l * E_ + e_] * ip[(long)l * E_];
            sQ[bi * SST + e_] = acc;
        }
    }
    __syncthreads();
    if (tid < NROW) {
        int bi = tid / N_;
        const float* hp = sH + tid * HST;
        const float* qp = sS + bi * SST;
        float d = 0.f;
        for (int e4 = 0; e4 < 25; e4++) {
            float4 hv = *(const float4*)(hp + e4 * 4);
            float4 qv = *(const float4*)(qp + e4 * 4);
            d += hv.x * qv.x + hv.y * qv.y + hv.z * qv.z + hv.w * qv.w;
        }
        sGp[tid] = d;
    }
    __syncthreads();
    if (tid < NB) {
        const float* lp = sGp + tid * N_;
        float m = lp[0];
        for (int n = 1; n < N_; n++) m = fmaxf(m, lp[n]);
        float s = 0.f;
        float* pp = sG + tid * N_;
        for (int n = 0; n < N_; n++) { float ev = expf(lp[n] - m); pp[n] = ev; s += ev; }
        float inv = 1.f / s;
        for (int n = 0; n < N_; n++) pp[n] *= inv;
    }
    __syncthreads();
    {
        float* sU = sS + NB * SST;
        for (int i = tid; i < NB * E_; i += NTH) {
            int bi = i / E_, e_ = i % E_;
            float u = 0.f;
#pragma unroll
            for (int n = 0; n < N_; n++) u += sG[bi * N_ + n] * sH[(bi * N_ + n) * HST + e_];
            sU[bi * SST + e_] = u;
        }
    }
    __syncthreads();
    {
        const float* sQ = sS;
        const float* sU = sS + NB * SST;
        float ao = *a_out_p;
        for (int i = tid; i < NB * E_; i += NTH) {
            int bi = i / E_, f_ = i % E_;
            float acc = sQ[bi * SST + f_] + H_b[f_];
            const float* hw = H_w + f_ * E_;   // L2-resident, shared by all CTAs
            const float* up = sU + bi * SST;
            for (int e4 = 0; e4 < 25; e4++) {
                float4 hv = *(const float4*)(hw + e4 * 4);
                float4 uv = *(const float4*)(up + e4 * 4);
                acc += hv.x * uv.x + hv.y * uv.y + hv.z * uv.z + hv.w * uv.w;
            }
            g_ya[(long)(b0g + bi) * E_ + f_] = (acc >= 0.f) ? acc : ao * acc;
        }
    }
}

// ============================================================
// K3: convert R_w and g_ya into packed bf16 hi/lo pair rows
// ============================================================
__global__ void convert_kernel(const float* __restrict__ R_w) {
    int idx = blockIdx.x * 256 + threadIdx.x;
    const int RTOT = V_ * 60;
    if (idx < RTOT) {
        int v = idx / 60, p = idx % 60;
        uint32_t hi = 0, lo = 0;
        if (p < 50) {
            float2 rv = *(const float2*)(R_w + (long)v * E_ + 2 * p);
            split2(rv.x, rv.y, hi, lo);
        }
        g_Rhi[idx] = hi;
        g_Rlo[idx] = lo;
    } else if (idx < RTOT + B_ * 60) {
        int i = idx - RTOT;
        int b = i / 60, p = i % 60;
        uint32_t hi = 0, lo = 0;
        if (p < 50) {
            float2 yv = *(const float2*)(g_ya + (long)b * E_ + 2 * p);
            split2(yv.x, yv.y, hi, lo);
        }
        g_Yhi[i] = hi;
        g_Ylo[i] = lo;
    }
}

// ============================================================
// K4: out = ya @ R_w^T + R_b on HMMA (bf16x3). 128b x 128v tiles.
// ============================================================
#define O_AHI 0
#define O_ALO 30720
#define O_BHI 61440
#define O_BLO 92160
#define OUT_SMEM 122880

__global__ __launch_bounds__(256, 1) void out_mma_kernel(
    const float* __restrict__ R_b, float* __restrict__ out)
{
    extern __shared__ char smo[];
    const int tid = threadIdx.x;
    const int w = tid >> 5;
    const int lane = tid & 31;
    const int v0 = blockIdx.x * 128;
    const int b0 = blockIdx.y * 128;
    const uint32_t smb = smem_u32(smo);

    uint32_t* sAhi = (uint32_t*)(smo + O_AHI);
    uint32_t* sAlo = (uint32_t*)(smo + O_ALO);
    uint32_t* sBhi = (uint32_t*)(smo + O_BHI);
    uint32_t* sBlo = (uint32_t*)(smo + O_BLO);
    for (int i = tid; i < 128 * 60; i += 256) {
        int r = i / 60, p = i % 60;
        sAhi[i] = g_Yhi[(b0 + r) * 60 + p];
        sAlo[i] = g_Ylo[(b0 + r) * 60 + p];
        sBhi[i] = g_Rhi[(long)(v0 + r) * 60 + p];
        sBlo[i] = g_Rlo[(long)(v0 + r) * 60 + p];
    }
    __syncthreads();

    const int mw = w >> 1, nw = w & 1;
    const int m0 = mw * 32;
    const int n0 = nw * 64;
    const int qr = lane >> 2, qc = lane & 3;
    const int grp = lane >> 3, lr = lane & 7;

    float acc[2][8][4];
#pragma unroll
    for (int mh = 0; mh < 2; mh++)
#pragma unroll
        for (int j = 0; j < 8; j++)
#pragma unroll
            for (int q = 0; q < 4; q++) acc[mh][j][q] = 0.f;

#pragma unroll
    for (int k = 0; k < 7; k++) {
        uint32_t ah[2][4], al[2][4];
#pragma unroll
        for (int mh = 0; mh < 2; mh++) {
            uint32_t aaddr = smb + O_AHI + (uint32_t)((m0 + 16 * mh + lr + ((grp & 1) << 3)) * 240
                           + k * 32 + ((grp >> 1) << 4));
            ldsm4(ah[mh], aaddr);
            ldsm4(al[mh], aaddr + 30720u);
        }
#pragma unroll
        for (int pq = 0; pq < 4; pq++) {
            uint32_t addr = smb + O_BHI + (uint32_t)((n0 + pq * 16 + lr + (grp >> 1) * 8) * 240
                          + k * 32 + (grp & 1) * 16);
            uint32_t bh[4], bl[4];
            ldsm4(bh, addr);
            ldsm4(bl, addr + 30720u);
#pragma unroll
            for (int mh = 0; mh < 2; mh++)
#pragma unroll
                for (int jj = 0; jj < 2; jj++) {
                    int j = pq * 2 + jj;
                    mma16816(acc[mh][j], ah[mh], &bh[2 * jj]);
                    mma16816(acc[mh][j], al[mh], &bh[2 * jj]);
                    mma16816(acc[mh][j], ah[mh], &bl[2 * jj]);
                }
        }
    }

#pragma unroll
    for (int mh = 0; mh < 2; mh++) {
        int ra = b0 + m0 + 16 * mh + qr;
        int rb2 = ra + 8;
#pragma unroll
        for (int j = 0; j < 8; j++) {
            int c = v0 + n0 + j * 8 + 2 * qc;
            float2 rb = *(const float2*)(R_b + c);
            float2 o0 = make_float2(acc[mh][j][0] + rb.x, acc[mh][j][1] + rb.y);
            float2 o1 = make_float2(acc[mh][j][2] + rb.x, acc[mh][j][3] + rb.y);
            *(float2*)(out + (long)ra * V_ + c) = o0;
            *(float2*)(out + (long)rb2 * V_ + c) = o1;
        }
    }
}

// ============================================================
extern "C" void kernel_launch(void* const* d_in, const int* in_sizes, int n_in,
                              void* d_out, int out_size) {
    const float* in_data = (const float*)d_in[0];
    const float* f       = (const float*)d_in[1];
    const float* h0      = (const float*)d_in[2];
    const float* w_mem   = (const float*)d_in[3];
    const float* U_w     = (const float*)d_in[4];
    const float* V_w     = (const float*)d_in[5];
    const float* W_w     = (const float*)d_in[6];
    const float* a_dm    = (const float*)d_in[7];
    const float* H_w     = (const float*)d_in[8];
    const float* H_b     = (const float*)d_in[9];
    const float* R_w     = (const float*)d_in[10];
    const float* R_b     = (const float*)d_in[11];
    const float* a_out   = (const float*)d_in[12];
    float* out = (float*)d_out;

    cudaFuncSetAttribute(scan_mma_kernel, cudaFuncAttributeMaxDynamicSharedMemorySize,
                         SCAN_SMEM);
    cudaFuncSetAttribute(out_mma_kernel, cudaFuncAttributeMaxDynamicSharedMemorySize,
                         OUT_SMEM);

    scan_mma_kernel<<<B_ / NB, NTH, SCAN_SMEM>>>(U_w, V_w, W_w, w_mem, h0, a_dm,
                                                 in_data, f, H_w, H_b, a_out);
    const int conv_total = V_ * 60 + B_ * 60;
    convert_kernel<<<(conv_total + 255) / 256, 256>>>(R_w);
    dim3 g4(V_ / 128, B_ / 128);
    out_mma_kernel<<<g4, 256, OUT_SMEM>>>(R_b, out);
}

// round 15
// speedup vs baseline: 1.1773x; 1.1773x over previous
#include <cuda_runtime.h>
#include <cuda_bf16.h>
#include <cuda_fp16.h>
#include <math.h>
#include <stdint.h>

#define B_   512
#define T_   1005
#define E_   100
#define L_   10
#define N_   20
#define V_   32000
#define NCH  100      // n_full = T/L
#define REST 5        // T % L

// ---- scratch (no allocations allowed) ----
__device__ float g_ya[B_ * E_];                 // prelu(y)
__device__ uint32_t g_Rhi[V_ * 60];             // R_w bf16-hi pairs, 240B rows
__device__ uint32_t g_Rlo[V_ * 60];
__device__ uint32_t g_Yhi[B_ * 60];             // ya bf16-hi pairs
__device__ uint32_t g_Ylo[B_ * 60];

// ---- warp MMA helpers (portable PTX, sm_80+) ----
__device__ __forceinline__ uint32_t smem_u32(const void* p) {
    uint32_t a;
    asm("{ .reg .u64 t; cvta.to.shared.u64 t, %1; cvt.u32.u64 %0, t; }"
        : "=r"(a) : "l"(p));
    return a;
}
__device__ __forceinline__ void ldsm4(uint32_t* r, uint32_t a) {
    asm volatile("ldmatrix.sync.aligned.m8n8.x4.shared.b16 {%0,%1,%2,%3}, [%4];"
        : "=r"(r[0]), "=r"(r[1]), "=r"(r[2]), "=r"(r[3]) : "r"(a));
}
__device__ __forceinline__ void ldsm2(uint32_t* r, uint32_t a) {
    asm volatile("ldmatrix.sync.aligned.m8n8.x2.shared.b16 {%0,%1}, [%2];"
        : "=r"(r[0]), "=r"(r[1]) : "r"(a));
}
// bf16 MMA (out GEMM)
__device__ __forceinline__ void mma16816(float* c, const uint32_t* a, const uint32_t* b) {
    asm volatile(
        "mma.sync.aligned.m16n8k16.row.col.f32.bf16.bf16.f32 "
        "{%0,%1,%2,%3}, {%4,%5,%6,%7}, {%8,%9}, {%0,%1,%2,%3};"
        : "+f"(c[0]), "+f"(c[1]), "+f"(c[2]), "+f"(c[3])
        : "r"(a[0]), "r"(a[1]), "r"(a[2]), "r"(a[3]), "r"(b[0]), "r"(b[1]));
}
// fp16 MMA (scan GEMM)
__device__ __forceinline__ void mma16816h(float* c, const uint32_t* a, const uint32_t* b) {
    asm volatile(
        "mma.sync.aligned.m16n8k16.row.col.f32.f16.f16.f32 "
        "{%0,%1,%2,%3}, {%4,%5,%6,%7}, {%8,%9}, {%0,%1,%2,%3};"
        : "+f"(c[0]), "+f"(c[1]), "+f"(c[2]), "+f"(c[3])
        : "r"(a[0]), "r"(a[1]), "r"(a[2]), "r"(a[3]), "r"(b[0]), "r"(b[1]));
}
// split two fp32 into packed bf16 hi + residual lo (out GEMM convert)
__device__ __forceinline__ void split2(float x0, float x1, uint32_t& hi, uint32_t& lo) {
    __nv_bfloat162 bh = __floats2bfloat162_rn(x0, x1);
    uint32_t h = *reinterpret_cast<uint32_t*>(&bh);
    float hf0 = __uint_as_float(h << 16);
    float hf1 = __uint_as_float(h & 0xffff0000u);
    __nv_bfloat162 bl = __floats2bfloat162_rn(x0 - hf0, x1 - hf1);
    hi = h;
    lo = *reinterpret_cast<uint32_t*>(&bl);
}
// pack two fp32 into fp16x2
__device__ __forceinline__ uint32_t pack_h2(float x0, float x1) {
    __half2 h2 = __floats2half2_rn(x0, x1);
    return *reinterpret_cast<uint32_t*>(&h2);
}

// ============================================================
// K2: persistent scan on warp MMA (plain fp16 HMMA).
//     128 CTAs x 4 batches; 10 MMA + 6 helper warps; infos and
//     attention+head fused. W staged TRANSPOSED (conflict-free).
// ============================================================
#define NB   4
#define NTH  512
#define BST  240
#define HST  108
#define SST  104

#define OFF_AHI 0                          // 19200
#define OFF_BHI 19200                      // 26880 -> 46080
#define OFF_H   46080                      // 34560 -> 80640
#define OFF_W   80640                      // 100*104*4 = 41600 -> 122240 (W^T / H_w)
#define OFF_WM  122240                     // 8320 -> 130560
#define OFF_VW  130560                     // 8320 -> 138880
#define OFF_S   138880                     // 3328 -> 142208
#define OFF_SSW 142208                     // 1664 -> 143872
#define OFF_G   143872                     // 320 -> 144192
#define OFF_GP  144192                     // 640 -> 144832
#define OFF_F   144832                     // 4000 -> 148832
#define SCAN_SMEM 148832

__global__ __launch_bounds__(NTH, 1) void scan_mma_kernel(
    const float* __restrict__ U_w, const float* __restrict__ V_w,
    const float* __restrict__ W_w, const float* __restrict__ w_mem,
    const float* __restrict__ h0,  const float* __restrict__ a_dm_p,
    const float* __restrict__ in_data, const float* __restrict__ f_w,
    const float* __restrict__ H_w, const float* __restrict__ H_b,
    const float* __restrict__ a_out_p)
{
    extern __shared__ char smc[];
    float* sH  = (float*)(smc + OFF_H);
    float* sW  = (float*)(smc + OFF_W);   // scan: W^T [e][f] stride SST; tail: H_w row-major
    float* sWm = (float*)(smc + OFF_WM);
    float* sVw = (float*)(smc + OFF_VW);
    float* sS  = (float*)(smc + OFF_S);
    float* sSW = (float*)(smc + OFF_SSW);
    float* sG  = (float*)(smc + OFF_G);
    float* sGp = (float*)(smc + OFF_GP);
    float* sF  = (float*)(smc + OFF_F);

    const int tid = threadIdx.x;
    const int w = tid >> 5;
    const int lane = tid & 31;
    const int b0g = blockIdx.x * NB;
    const float adm = *a_dm_p;
    const uint32_t smb = smem_u32(smc);

    // ---- zero A+B tiles (pad rows/cols must stay zero) ----
    for (int i = tid; i < OFF_H / 4; i += NTH) ((uint32_t*)smc)[i] = 0;
    __syncthreads();

    // ---- stage U (fp16), W^T, w_mem, f, h init + A tile from h0 ----
    for (int i = tid; i < E_ * 50; i += NTH) {
        int f_ = i / 50, p = i % 50;
        float2 uv = *(const float2*)(U_w + f_ * E_ + 2 * p);
        *(uint32_t*)(smc + OFF_BHI + f_ * BST + p * 4) = pack_h2(uv.x, uv.y);
    }
    for (int i = tid; i < E_ * E_; i += NTH) {
        int f_ = i / E_, e_ = i % E_;
        sW[e_ * SST + f_] = W_w[i];     // transposed: [e][f]
    }
    for (int i = tid; i < L_ * E_; i += NTH) sF[i] = f_w[i];
    for (int i = tid; i < N_ * E_; i += NTH) {
        int n_ = i / E_, e_ = i % E_;
        sWm[n_ * SST + e_] = w_mem[i];
    }
    for (int i = tid; i < 80 * 50; i += NTH) {
        int row = i / 50, p = i % 50;
        float2 hv = *(const float2*)(h0 + (row % N_) * E_ + 2 * p);
        *(float2*)(sH + row * HST + 2 * p) = hv;
        *(uint32_t*)(smc + OFF_AHI + row * BST + p * 4) = pack_h2(hv.x, hv.y);
    }
    if (tid < 80) { sGp[2 * tid] = 1.f; sGp[2 * tid + 1] = 0.f; }
    __syncthreads();
    // Vw[n][f] = w_mem[n] . V_w[f] (one-time)
    for (int i = tid; i < N_ * E_; i += NTH) {
        int n_ = i / E_, f_ = i % E_;
        float acc = 0.f;
        for (int e_ = 0; e_ < E_; e_++) acc += sWm[n_ * SST + e_] * V_w[f_ * E_ + e_];
        sVw[n_ * SST + f_] = acc;
    }
    // s_0 = infos(t=0)
    for (int i = tid; i < NB * E_; i += NTH) {
        int bi = i / E_, e_ = i % E_;
        const float* ip = in_data + (long)(b0g + bi) * T_ * E_ + e_;
        float acc = 0.f;
#pragma unroll
        for (int l = 0; l < L_; l++) acc += sF[l * E_ + e_] * ip[(long)l * E_];
        sS[bi * SST + e_] = acc;
    }
    __syncthreads();

    const int stripe = w >> 1, nh = w & 1;
    const int m0 = stripe * 16;
    const int qr = lane >> 2, qc = lane & 3;
    const int r0 = m0 + qr, r1 = r0 + 8;
    const int grp = lane >> 3, lr = lane & 7;

    const int pf0 = tid - 320;
    const int pf1 = pf0 + 192;
    const int pf2 = pf0 + 384;
    const bool pfh2 = (pf0 >= 0) && (pf2 < NB * E_);

    for (int t = 0; t < NCH; t++) {
        const float* sScur = sS + (t & 1) * NB * SST;

        float acc[7][4];
        float inv0 = 0.f, inv1 = 0.f;
        float v0[10], v1[10], v2[10];

        // ================= phase A: fp16 MMA | helpers ====================
        if (w < 10) {
            inv0 = rsqrtf(sGp[2 * r0] + sGp[2 * r0 + 1]);
            inv1 = rsqrtf(sGp[2 * r1] + sGp[2 * r1 + 1]);
#pragma unroll
            for (int j = 0; j < 7; j++)
#pragma unroll
                for (int q = 0; q < 4; q++) acc[j][q] = 0.f;
            const uint32_t aBase = smb + OFF_AHI;
            const uint32_t bhBase = smb + OFF_BHI;
#pragma unroll
            for (int k = 0; k < 7; k++) {
                uint32_t ah[4];
                uint32_t aaddr = aBase + (uint32_t)((m0 + lr + ((grp & 1) << 3)) * BST
                               + k * 32 + ((grp >> 1) << 4));
                ldsm4(ah, aaddr);
                uint32_t bh[14];
#pragma unroll
                for (int pq = 0; pq < 3; pq++) {
                    int t0 = nh * 7 + pq * 2;
                    uint32_t addr = bhBase + (uint32_t)((t0 * 8 + lr + (grp >> 1) * 8) * BST
                                  + k * 32 + (grp & 1) * 16);
                    ldsm4(&bh[pq * 4], addr);
                }
#pragma unroll
                for (int j = 0; j < 6; j++) {
                    mma16816h(acc[j], ah, &bh[2 * j]);
                }
                if (nh == 0) {   // tail tile j=6 (cols 48-55)
                    uint32_t addr = bhBase + (uint32_t)((6 * 8 + lr) * BST
                                  + k * 32 + ((lane >> 3) & 1) * 16);
                    uint32_t bht[2];
                    ldsm2(bht, addr);
                    mma16816h(acc[6], ah, bht);
                }
            }
        } else {
            if (t + 1 < NCH) {
                int bi0 = pf0 / E_, e0 = pf0 % E_;
                int bi1 = pf1 / E_, e1 = pf1 % E_;
                const float* ip0 = in_data + ((long)(b0g + bi0) * T_ + (t + 1) * L_) * E_ + e0;
                const float* ip1 = in_data + ((long)(b0g + bi1) * T_ + (t + 1) * L_) * E_ + e1;
#pragma unroll
                for (int l = 0; l < L_; l++) v0[l] = ip0[(long)l * E_];
#pragma unroll
                for (int l = 0; l < L_; l++) v1[l] = ip1[(long)l * E_];
                if (pfh2) {
                    int bi2 = pf2 / E_, e2 = pf2 % E_;
                    const float* ip2 = in_data + ((long)(b0g + bi2) * T_ + (t + 1) * L_) * E_ + e2;
#pragma unroll
                    for (int l = 0; l < L_; l++) v2[l] = ip2[(long)l * E_];
                }
            }
            int i = pf0;
            if (i < 100) {
                // sSW[bi][f=i] = s[bi] . W[f]  — W^T coalesced, s broadcast
                int f_ = i;
                float a0 = 0.f, a1 = 0.f, a2 = 0.f, a3 = 0.f;
#pragma unroll 2
                for (int p = 0; p < 50; p++) {
                    float w0 = sW[(2 * p) * SST + f_];
                    float w1 = sW[(2 * p + 1) * SST + f_];
                    float2 s0 = *(const float2*)(sScur + 0 * SST + 2 * p);
                    float2 s1 = *(const float2*)(sScur + 1 * SST + 2 * p);
                    float2 s2 = *(const float2*)(sScur + 2 * SST + 2 * p);
                    float2 s3 = *(const float2*)(sScur + 3 * SST + 2 * p);
                    a0 += w0 * s0.x + w1 * s0.y;
                    a1 += w0 * s1.x + w1 * s1.y;
                    a2 += w0 * s2.x + w1 * s2.y;
                    a3 += w0 * s3.x + w1 * s3.y;
                }
                sSW[0 * SST + f_] = a0;
                sSW[1 * SST + f_] = a1;
                sSW[2 * SST + f_] = a2;
                sSW[3 * SST + f_] = a3;
            } else if (i < 180) {
                int row = i - 100;
                int bi = row / N_, ne = row % N_;
                const float* hp = sH + row * HST;
                const float* wp = sWm + ne * SST;
                const float* sp = sScur + bi * SST;
                float hs = 0.f, ws = 0.f;
                for (int e4 = 0; e4 < 25; e4++) {
                    float4 hv = *(const float4*)(hp + e4 * 4);
                    float4 wv = *(const float4*)(wp + e4 * 4);
                    float4 sv = *(const float4*)(sp + e4 * 4);
                    hs += hv.x * sv.x + hv.y * sv.y + hv.z * sv.z + hv.w * sv.w;
                    ws += wv.x * sv.x + wv.y * sv.y + wv.z * sv.z + wv.w * sv.w;
                }
                float inv = rsqrtf(sGp[2 * row] + sGp[2 * row + 1]);
                sG[row] = 1.f / (1.f + expf(-(inv * hs + ws)));
            }
        }
        __syncthreads();

        // ================= phase B: epilogue + A-tile store ===============
        if (w < 10) {
            float g0 = sG[r0], g1 = sG[r1];
            int bi0 = r0 / N_, ne0 = r0 % N_;
            int bi1 = r1 / N_, ne1 = r1 % N_;
            float ssq0 = 0.f, ssq1 = 0.f;
#pragma unroll
            for (int j = 0; j < 7; j++) {
                int f0 = (nh * 7 + j) * 8 + 2 * qc;
                if (f0 < 100) {
                    float2 vw0 = *(const float2*)(sVw + ne0 * SST + f0);
                    float2 sw0 = *(const float2*)(sSW + bi0 * SST + f0);
                    float2 hv0 = *(const float2*)(sH + r0 * HST + f0);
                    float c0 = acc[j][0] * inv0 + vw0.x + sw0.x;
                    float c1 = acc[j][1] * inv0 + vw0.y + sw0.y;
                    c0 = (c0 >= 0.f) ? c0 : adm * c0;
                    c1 = (c1 >= 0.f) ? c1 : adm * c1;
                    float n0v = hv0.x * inv0 + g0 * c0;
                    float n1v = hv0.y * inv0 + g0 * c1;
                    *(float2*)(sH + r0 * HST + f0) = make_float2(n0v, n1v);
                    ssq0 += n0v * n0v + n1v * n1v;
                    *(uint32_t*)(smc + OFF_AHI + r0 * BST + f0 * 2) = pack_h2(n0v, n1v);

                    float2 vw1 = *(const float2*)(sVw + ne1 * SST + f0);
                    float2 sw1 = *(const float2*)(sSW + bi1 * SST + f0);
                    float2 hv1 = *(const float2*)(sH + r1 * HST + f0);
                    float d0 = acc[j][2] * inv1 + vw1.x + sw1.x;
                    float d1 = acc[j][3] * inv1 + vw1.y + sw1.y;
                    d0 = (d0 >= 0.f) ? d0 : adm * d0;
                    d1 = (d1 >= 0.f) ? d1 : adm * d1;
                    float m0v = hv1.x * inv1 + g1 * d0;
                    float m1v = hv1.y * inv1 + g1 * d1;
                    *(float2*)(sH + r1 * HST + f0) = make_float2(m0v, m1v);
                    ssq1 += m0v * m0v + m1v * m1v;
                    *(uint32_t*)(smc + OFF_AHI + r1 * BST + f0 * 2) = pack_h2(m0v, m1v);
                }
            }
            ssq0 += __shfl_xor_sync(0xffffffffu, ssq0, 1);
            ssq0 += __shfl_xor_sync(0xffffffffu, ssq0, 2);
            ssq1 += __shfl_xor_sync(0xffffffffu, ssq1, 1);
            ssq1 += __shfl_xor_sync(0xffffffffu, ssq1, 2);
            if (qc == 0) {
                sGp[2 * r0 + nh] = ssq0;
                sGp[2 * r1 + nh] = ssq1;
            }
        } else if (t + 1 < NCH) {
            float* sNxt = sS + ((t + 1) & 1) * NB * SST;
            int bi0 = pf0 / E_, e0 = pf0 % E_;
            int bi1 = pf1 / E_, e1 = pf1 % E_;
            float a = 0.f, b = 0.f;
#pragma unroll
            for (int l = 0; l < L_; l++) a += sF[l * E_ + e0] * v0[l];
#pragma unroll
            for (int l = 0; l < L_; l++) b += sF[l * E_ + e1] * v1[l];
            sNxt[bi0 * SST + e0] = a;
            sNxt[bi1 * SST + e1] = b;
            if (pfh2) {
                int bi2 = pf2 / E_, e2 = pf2 % E_;
                float c = 0.f;
#pragma unroll
                for (int l = 0; l < L_; l++) c += sF[l * E_ + e2] * v2[l];
                sNxt[bi2 * SST + e2] = c;
            }
        }
        __syncthreads();
    }

    // ================= fused attention + head ==========================
    if (tid < 80) sG[tid] = rsqrtf(sGp[2 * tid] + sGp[2 * tid + 1]);
    __syncthreads();
    for (int i = tid; i < 80 * E_; i += NTH) {
        int row = i / E_, e_ = i % E_;
        sH[row * HST + e_] *= sG[row];
    }
    {
        float* sQ = sS;
        for (int i = tid; i < NB * E_; i += NTH) {
            int bi = i / E_, e_ = i % E_;
            const float* ip = in_data + ((long)(b0g + bi) * T_ + NCH * L_) * E_ + e_;
            float acc = 0.f;
#pragma unroll
            for (int l = 0; l < REST; l++) acc += sF[l * E_ + e_] * ip[(long)l * E_];
            sQ[bi * SST + e_] = acc;
        }
    }
    for (int i = tid; i < E_ * E_; i += NTH) sW[i] = H_w[i];   // reuse as row-major H_w
    __syncthreads();
    if (tid < 80) {
        int bi = tid / N_;
        const float* hp = sH + tid * HST;
        const float* qp = sS + bi * SST;
        float d = 0.f;
        for (int e4 = 0; e4 < 25; e4++) {
            float4 hv = *(const float4*)(hp + e4 * 4);
            float4 qv = *(const float4*)(qp + e4 * 4);
            d += hv.x * qv.x + hv.y * qv.y + hv.z * qv.z + hv.w * qv.w;
        }
        sGp[tid] = d;
    }
    __syncthreads();
    if (tid < NB) {
        const float* lp = sGp + tid * N_;
        float m = lp[0];
        for (int n = 1; n < N_; n++) m = fmaxf(m, lp[n]);
        float s = 0.f;
        float* pp = sG + tid * N_;
        for (int n = 0; n < N_; n++) { float ev = expf(lp[n] - m); pp[n] = ev; s += ev; }
        float inv = 1.f / s;
        for (int n = 0; n < N_; n++) pp[n] *= inv;
    }
    __syncthreads();
    {
        float* sU = sS + NB * SST;
        for (int i = tid; i < NB * E_; i += NTH) {
            int bi = i / E_, e_ = i % E_;
            float u = 0.f;
#pragma unroll
            for (int n = 0; n < N_; n++) u += sG[bi * N_ + n] * sH[(bi * N_ + n) * HST + e_];
            sU[bi * SST + e_] = u;
        }
    }
    __syncthreads();
    {
        const float* sQ = sS;
        const float* sU = sS + NB * SST;
        float ao = *a_out_p;
        for (int i = tid; i < NB * E_; i += NTH) {
            int bi = i / E_, f_ = i % E_;
            float acc = sQ[bi * SST + f_] + H_b[f_];
            const float* hw = sW + f_ * E_;
            const float* up = sU + bi * SST;
            for (int e4 = 0; e4 < 25; e4++) {
                float4 hv = *(const float4*)(hw + e4 * 4);
                float4 uv = *(const float4*)(up + e4 * 4);
                acc += hv.x * uv.x + hv.y * uv.y + hv.z * uv.z + hv.w * uv.w;
            }
            g_ya[(long)(b0g + bi) * E_ + f_] = (acc >= 0.f) ? acc : ao * acc;
        }
    }
}

// ============================================================
// K3: convert R_w and g_ya into packed bf16 hi/lo pair rows
// ============================================================
__global__ void convert_kernel(const float* __restrict__ R_w) {
    int idx = blockIdx.x * 256 + threadIdx.x;
    const int RTOT = V_ * 60;
    if (idx < RTOT) {
        int v = idx / 60, p = idx % 60;
        uint32_t hi = 0, lo = 0;
        if (p < 50) {
            float2 rv = *(const float2*)(R_w + (long)v * E_ + 2 * p);
            split2(rv.x, rv.y, hi, lo);
        }
        g_Rhi[idx] = hi;
        g_Rlo[idx] = lo;
    } else if (idx < RTOT + B_ * 60) {
        int i = idx - RTOT;
        int b = i / 60, p = i % 60;
        uint32_t hi = 0, lo = 0;
        if (p < 50) {
            float2 yv = *(const float2*)(g_ya + (long)b * E_ + 2 * p);
            split2(yv.x, yv.y, hi, lo);
        }
        g_Yhi[i] = hi;
        g_Ylo[i] = lo;
    }
}

// ============================================================
// K4: out = ya @ R_w^T + R_b on HMMA (bf16x3). 128b x 128v tiles.
// ============================================================
#define O_AHI 0
#define O_ALO 30720
#define O_BHI 61440
#define O_BLO 92160
#define OUT_SMEM 122880

__global__ __launch_bounds__(256, 1) void out_mma_kernel(
    const float* __restrict__ R_b, float* __restrict__ out)
{
    extern __shared__ char smo[];
    const int tid = threadIdx.x;
    const int w = tid >> 5;
    const int lane = tid & 31;
    const int v0 = blockIdx.x * 128;
    const int b0 = blockIdx.y * 128;
    const uint32_t smb = smem_u32(smo);

    uint32_t* sAhi = (uint32_t*)(smo + O_AHI);
    uint32_t* sAlo = (uint32_t*)(smo + O_ALO);
    uint32_t* sBhi = (uint32_t*)(smo + O_BHI);
    uint32_t* sBlo = (uint32_t*)(smo + O_BLO);
    for (int i = tid; i < 128 * 60; i += 256) {
        int r = i / 60, p = i % 60;
        sAhi[i] = g_Yhi[(b0 + r) * 60 + p];
        sAlo[i] = g_Ylo[(b0 + r) * 60 + p];
        sBhi[i] = g_Rhi[(long)(v0 + r) * 60 + p];
        sBlo[i] = g_Rlo[(long)(v0 + r) * 60 + p];
    }
    __syncthreads();

    const int mw = w >> 1, nw = w & 1;
    const int m0 = mw * 32;
    const int n0 = nw * 64;
    const int qr = lane >> 2, qc = lane & 3;
    const int grp = lane >> 3, lr = lane & 7;

    float acc[2][8][4];
#pragma unroll
    for (int mh = 0; mh < 2; mh++)
#pragma unroll
        for (int j = 0; j < 8; j++)
#pragma unroll
            for (int q = 0; q < 4; q++) acc[mh][j][q] = 0.f;

#pragma unroll
    for (int k = 0; k < 7; k++) {
        uint32_t ah[2][4], al[2][4];
#pragma unroll
        for (int mh = 0; mh < 2; mh++) {
            uint32_t aaddr = smb + O_AHI + (uint32_t)((m0 + 16 * mh + lr + ((grp & 1) << 3)) * 240
                           + k * 32 + ((grp >> 1) << 4));
            ldsm4(ah[mh], aaddr);
            ldsm4(al[mh], aaddr + 30720u);
        }
#pragma unroll
        for (int pq = 0; pq < 4; pq++) {
            uint32_t addr = smb + O_BHI + (uint32_t)((n0 + pq * 16 + lr + (grp >> 1) * 8) * 240
                          + k * 32 + (grp & 1) * 16);
            uint32_t bh[4], bl[4];
            ldsm4(bh, addr);
            ldsm4(bl, addr + 30720u);
#pragma unroll
            for (int mh = 0; mh < 2; mh++)
#pragma unroll
                for (int jj = 0; jj < 2; jj++) {
                    int j = pq * 2 + jj;
                    mma16816(acc[mh][j], ah[mh], &bh[2 * jj]);
                    mma16816(acc[mh][j], al[mh], &bh[2 * jj]);
                    mma16816(acc[mh][j], ah[mh], &bl[2 * jj]);
                }
        }
    }

#pragma unroll
    for (int mh = 0; mh < 2; mh++) {
        int ra = b0 + m0 + 16 * mh + qr;
        int rb2 = ra + 8;
#pragma unroll
        for (int j = 0; j < 8; j++) {
            int c = v0 + n0 + j * 8 + 2 * qc;
            float2 rb = *(const float2*)(R_b + c);
            float2 o0 = make_float2(acc[mh][j][0] + rb.x, acc[mh][j][1] + rb.y);
            float2 o1 = make_float2(acc[mh][j][2] + rb.x, acc[mh][j][3] + rb.y);
            *(float2*)(out + (long)ra * V_ + c) = o0;
            *(float2*)(out + (long)rb2 * V_ + c) = o1;
        }
    }
}

// ============================================================
extern "C" void kernel_launch(void* const* d_in, const int* in_sizes, int n_in,
                              void* d_out, int out_size) {
    const float* in_data = (const float*)d_in[0];
    const float* f       = (const float*)d_in[1];
    const float* h0      = (const float*)d_in[2];
    const float* w_mem   = (const float*)d_in[3];
    const float* U_w     = (const float*)d_in[4];
    const float* V_w     = (const float*)d_in[5];
    const float* W_w     = (const float*)d_in[6];
    const float* a_dm    = (const float*)d_in[7];
    const float* H_w     = (const float*)d_in[8];
    const float* H_b     = (const float*)d_in[9];
    const float* R_w     = (const float*)d_in[10];
    const float* R_b     = (const float*)d_in[11];
    const float* a_out   = (const float*)d_in[12];
    float* out = (float*)d_out;

    cudaFuncSetAttribute(scan_mma_kernel, cudaFuncAttributeMaxDynamicSharedMemorySize,
                         SCAN_SMEM);
    cudaFuncSetAttribute(out_mma_kernel, cudaFuncAttributeMaxDynamicSharedMemorySize,
                         OUT_SMEM);

    scan_mma_kernel<<<B_ / NB, NTH, SCAN_SMEM>>>(U_w, V_w, W_w, w_mem, h0, a_dm,
                                                 in_data, f, H_w, H_b, a_out);
    const int conv_total = V_ * 60 + B_ * 60;
    convert_kernel<<<(conv_total + 255) / 256, 256>>>(R_w);
    dim3 g4(V_ / 128, B_ / 128);
    out_mma_kernel<<<g4, 256, OUT_SMEM>>>(R_b, out);
}

// round 16
// speedup vs baseline: 1.3430x; 1.1408x over previous
#include <cuda_runtime.h>
#include <cuda_bf16.h>
#include <cuda_fp16.h>
#include <math.h>
#include <stdint.h>

#define B_   512
#define T_   1005
#define E_   100
#define L_   10
#define N_   20
#define V_   32000
#define NCH  100      // n_full = T/L
#define REST 5        // T % L

// ---- scratch (no allocations allowed) ----
__device__ float g_ya[B_ * E_];                 // prelu(y)
__device__ uint32_t g_Rhi[V_ * 60];             // R_w bf16-hi pairs, 240B rows
__device__ uint32_t g_Rlo[V_ * 60];
__device__ uint32_t g_Yhi[B_ * 60];             // ya bf16-hi pairs
__device__ uint32_t g_Ylo[B_ * 60];

// ---- warp MMA helpers (portable PTX, sm_80+) ----
__device__ __forceinline__ uint32_t smem_u32(const void* p) {
    uint32_t a;
    asm("{ .reg .u64 t; cvta.to.shared.u64 t, %1; cvt.u32.u64 %0, t; }"
        : "=r"(a) : "l"(p));
    return a;
}
__device__ __forceinline__ void ldsm4(uint32_t* r, uint32_t a) {
    asm volatile("ldmatrix.sync.aligned.m8n8.x4.shared.b16 {%0,%1,%2,%3}, [%4];"
        : "=r"(r[0]), "=r"(r[1]), "=r"(r[2]), "=r"(r[3]) : "r"(a));
}
__device__ __forceinline__ void ldsm2(uint32_t* r, uint32_t a) {
    asm volatile("ldmatrix.sync.aligned.m8n8.x2.shared.b16 {%0,%1}, [%2];"
        : "=r"(r[0]), "=r"(r[1]) : "r"(a));
}
// bf16 MMA (out GEMM)
__device__ __forceinline__ void mma16816(float* c, const uint32_t* a, const uint32_t* b) {
    asm volatile(
        "mma.sync.aligned.m16n8k16.row.col.f32.bf16.bf16.f32 "
        "{%0,%1,%2,%3}, {%4,%5,%6,%7}, {%8,%9}, {%0,%1,%2,%3};"
        : "+f"(c[0]), "+f"(c[1]), "+f"(c[2]), "+f"(c[3])
        : "r"(a[0]), "r"(a[1]), "r"(a[2]), "r"(a[3]), "r"(b[0]), "r"(b[1]));
}
// fp16 MMA (scan GEMM)
__device__ __forceinline__ void mma16816h(float* c, const uint32_t* a, const uint32_t* b) {
    asm volatile(
        "mma.sync.aligned.m16n8k16.row.col.f32.f16.f16.f32 "
        "{%0,%1,%2,%3}, {%4,%5,%6,%7}, {%8,%9}, {%0,%1,%2,%3};"
        : "+f"(c[0]), "+f"(c[1]), "+f"(c[2]), "+f"(c[3])
        : "r"(a[0]), "r"(a[1]), "r"(a[2]), "r"(a[3]), "r"(b[0]), "r"(b[1]));
}
// split two fp32 into packed bf16 hi + residual lo (out GEMM convert)
__device__ __forceinline__ void split2(float x0, float x1, uint32_t& hi, uint32_t& lo) {
    __nv_bfloat162 bh = __floats2bfloat162_rn(x0, x1);
    uint32_t h = *reinterpret_cast<uint32_t*>(&bh);
    float hf0 = __uint_as_float(h << 16);
    float hf1 = __uint_as_float(h & 0xffff0000u);
    __nv_bfloat162 bl = __floats2bfloat162_rn(x0 - hf0, x1 - hf1);
    hi = h;
    lo = *reinterpret_cast<uint32_t*>(&bl);
}
// pack two fp32 into fp16x2
__device__ __forceinline__ uint32_t pack_h2(float x0, float x1) {
    __half2 h2 = __floats2half2_rn(x0, x1);
    return *reinterpret_cast<uint32_t*>(&h2);
}

// ============================================================
// K2: persistent scan on warp MMA (plain fp16 HMMA).
//     128 CTAs x 4 batches; 10 MMA + 6 helper warps.
//     h register-resident in MMA threads; gate dot fused into
//     the epilogue; infos and attention+head fused.
// ============================================================
#define NB   4
#define NTH  512
#define BST  240
#define HST  108
#define SST  104

#define OFF_AHI 0                          // 19200
#define OFF_BHI 19200                      // 26880 -> 46080
#define OFF_H   46080                      // 34560 -> 80640
#define OFF_W   80640                      // 40000 -> 120640
#define OFF_WM  120640                     // 8320 -> 128960
#define OFF_VW  128960                     // 8320 -> 137280
#define OFF_S   137280                     // 3328 -> 140608
#define OFF_SSW 140608                     // 1664 -> 142272
#define OFF_G   142272                     // 320 -> 142592
#define OFF_GP  142592                     // 640 -> 143232
#define OFF_F   143232                     // 4000 -> 147232
#define OFF_DOT 147232                     // 640 -> 147872
#define SCAN_SMEM 147872

__global__ __launch_bounds__(NTH, 1) void scan_mma_kernel(
    const float* __restrict__ U_w, const float* __restrict__ V_w,
    const float* __restrict__ W_w, const float* __restrict__ w_mem,
    const float* __restrict__ h0,  const float* __restrict__ a_dm_p,
    const float* __restrict__ in_data, const float* __restrict__ f_w,
    const float* __restrict__ H_w, const float* __restrict__ H_b,
    const float* __restrict__ a_out_p)
{
    extern __shared__ char smc[];
    float* sH  = (float*)(smc + OFF_H);
    float* sW  = (float*)(smc + OFF_W);
    float* sWm = (float*)(smc + OFF_WM);
    float* sVw = (float*)(smc + OFF_VW);
    float* sS  = (float*)(smc + OFF_S);
    float* sSW = (float*)(smc + OFF_SSW);
    float* sG  = (float*)(smc + OFF_G);
    float* sGp = (float*)(smc + OFF_GP);
    float* sF  = (float*)(smc + OFF_F);
    float* sDot= (float*)(smc + OFF_DOT);

    const int tid = threadIdx.x;
    const int w = tid >> 5;
    const int lane = tid & 31;
    const int b0g = blockIdx.x * NB;
    const float adm = *a_dm_p;
    const uint32_t smb = smem_u32(smc);

    // ---- zero A+B tiles (pad rows/cols must stay zero) ----
    for (int i = tid; i < OFF_H / 4; i += NTH) ((uint32_t*)smc)[i] = 0;
    __syncthreads();

    // ---- stage U (fp16), W, w_mem, f, h init + A tile from h0 ----
    for (int i = tid; i < E_ * 50; i += NTH) {
        int f_ = i / 50, p = i % 50;
        float2 uv = *(const float2*)(U_w + f_ * E_ + 2 * p);
        *(uint32_t*)(smc + OFF_BHI + f_ * BST + p * 4) = pack_h2(uv.x, uv.y);
    }
    for (int i = tid; i < E_ * E_; i += NTH) sW[i] = W_w[i];
    for (int i = tid; i < L_ * E_; i += NTH) sF[i] = f_w[i];
    for (int i = tid; i < N_ * E_; i += NTH) {
        int n_ = i / E_, e_ = i % E_;
        sWm[n_ * SST + e_] = w_mem[i];
    }
    for (int i = tid; i < 80 * 50; i += NTH) {
        int row = i / 50, p = i % 50;
        float2 hv = *(const float2*)(h0 + (row % N_) * E_ + 2 * p);
        *(float2*)(sH + row * HST + 2 * p) = hv;
        *(uint32_t*)(smc + OFF_AHI + row * BST + p * 4) = pack_h2(hv.x, hv.y);
    }
    if (tid < 80) { sGp[2 * tid] = 1.f; sGp[2 * tid + 1] = 0.f; }
    __syncthreads();
    // Vw[n][f] = w_mem[n] . V_w[f] (one-time)
    for (int i = tid; i < N_ * E_; i += NTH) {
        int n_ = i / E_, f_ = i % E_;
        float acc = 0.f;
        for (int e_ = 0; e_ < E_; e_++) acc += sWm[n_ * SST + e_] * V_w[f_ * E_ + e_];
        sVw[n_ * SST + f_] = acc;
    }
    // s_0 = infos(t=0)
    for (int i = tid; i < NB * E_; i += NTH) {
        int bi = i / E_, e_ = i % E_;
        const float* ip = in_data + (long)(b0g + bi) * T_ * E_ + e_;
        float acc = 0.f;
#pragma unroll
        for (int l = 0; l < L_; l++) acc += sF[l * E_ + e_] * ip[(long)l * E_];
        sS[bi * SST + e_] = acc;
    }
    __syncthreads();
    // sDot init: h0 . s0 per row
    for (int r = tid; r < 80; r += NTH) {
        const float* hp = sH + r * HST;
        const float* sp = sS + (r / N_) * SST;
        float d = 0.f;
        for (int e4 = 0; e4 < 25; e4++) {
            float4 hv = *(const float4*)(hp + e4 * 4);
            float4 sv = *(const float4*)(sp + e4 * 4);
            d += hv.x * sv.x + hv.y * sv.y + hv.z * sv.z + hv.w * sv.w;
        }
        sDot[2 * r] = d;
        sDot[2 * r + 1] = 0.f;
    }
    __syncthreads();

    const int stripe = w >> 1, nh = w & 1;
    const int m0 = stripe * 16;
    const int qr = lane >> 2, qc = lane & 3;
    const int r0 = m0 + qr, r1 = r0 + 8;
    const int grp = lane >> 3, lr = lane & 7;

    const int pf0 = tid - 320;
    const int pf1 = pf0 + 192;
    const int pf2 = pf0 + 384;
    const bool pfh2 = (pf0 >= 0) && (pf2 < NB * E_);

    // ---- h register-resident in MMA threads ----
    float hreg[7][4];
    if (w < 10) {
#pragma unroll
        for (int j = 0; j < 7; j++) {
            int f0 = (nh * 7 + j) * 8 + 2 * qc;
            if (f0 < 100) {
                float2 a = *(const float2*)(sH + r0 * HST + f0);
                float2 b = *(const float2*)(sH + r1 * HST + f0);
                hreg[j][0] = a.x; hreg[j][1] = a.y;
                hreg[j][2] = b.x; hreg[j][3] = b.y;
            }
        }
    }

    for (int t = 0; t < NCH; t++) {
        const float* sScur = sS + (t & 1) * NB * SST;

        float acc[7][4];
        float inv0 = 0.f, inv1 = 0.f;

        // ================= phase A: fp16 MMA | helpers ====================
        if (w < 10) {
            inv0 = rsqrtf(sGp[2 * r0] + sGp[2 * r0 + 1]);
            inv1 = rsqrtf(sGp[2 * r1] + sGp[2 * r1 + 1]);
#pragma unroll
            for (int j = 0; j < 7; j++)
#pragma unroll
                for (int q = 0; q < 4; q++) acc[j][q] = 0.f;
            const uint32_t aBase = smb + OFF_AHI;
            const uint32_t bhBase = smb + OFF_BHI;
#pragma unroll
            for (int k = 0; k < 7; k++) {
                uint32_t ah[4];
                uint32_t aaddr = aBase + (uint32_t)((m0 + lr + ((grp & 1) << 3)) * BST
                               + k * 32 + ((grp >> 1) << 4));
                ldsm4(ah, aaddr);
                uint32_t bh[14];
#pragma unroll
                for (int pq = 0; pq < 3; pq++) {
                    int t0 = nh * 7 + pq * 2;
                    uint32_t addr = bhBase + (uint32_t)((t0 * 8 + lr + (grp >> 1) * 8) * BST
                                  + k * 32 + (grp & 1) * 16);
                    ldsm4(&bh[pq * 4], addr);
                }
#pragma unroll
                for (int j = 0; j < 6; j++) {
                    mma16816h(acc[j], ah, &bh[2 * j]);
                }
                if (nh == 0) {   // tail tile j=6 (cols 48-55)
                    uint32_t addr = bhBase + (uint32_t)((6 * 8 + lr) * BST
                                  + k * 32 + ((lane >> 3) & 1) * 16);
                    uint32_t bht[2];
                    ldsm2(bht, addr);
                    mma16816h(acc[6], ah, bht);
                }
            }
        } else {
            float v0[10], v1[10], v2[10];
            if (t + 1 < NCH) {
                int bi0 = pf0 / E_, e0 = pf0 % E_;
                int bi1 = pf1 / E_, e1 = pf1 % E_;
                const float* ip0 = in_data + ((long)(b0g + bi0) * T_ + (t + 1) * L_) * E_ + e0;
                const float* ip1 = in_data + ((long)(b0g + bi1) * T_ + (t + 1) * L_) * E_ + e1;
#pragma unroll
                for (int l = 0; l < L_; l++) v0[l] = ip0[(long)l * E_];
#pragma unroll
                for (int l = 0; l < L_; l++) v1[l] = ip1[(long)l * E_];
                if (pfh2) {
                    int bi2 = pf2 / E_, e2 = pf2 % E_;
                    const float* ip2 = in_data + ((long)(b0g + bi2) * T_ + (t + 1) * L_) * E_ + e2;
#pragma unroll
                    for (int l = 0; l < L_; l++) v2[l] = ip2[(long)l * E_];
                }
            }
            int i = pf0;
            if (i < 100) {
                // sSW[bi][f=i] = s[bi] . W[f]  (row-major W, LDS.128)
                int f_ = i;
                float a0 = 0.f, a1 = 0.f, a2 = 0.f, a3 = 0.f;
                const float* wp = sW + f_ * E_;
                for (int e4 = 0; e4 < 25; e4++) {
                    float4 wv = *(const float4*)(wp + e4 * 4);
                    float4 s0 = *(const float4*)(sScur + 0 * SST + e4 * 4);
                    float4 s1 = *(const float4*)(sScur + 1 * SST + e4 * 4);
                    float4 s2 = *(const float4*)(sScur + 2 * SST + e4 * 4);
                    float4 s3 = *(const float4*)(sScur + 3 * SST + e4 * 4);
                    a0 += wv.x * s0.x + wv.y * s0.y + wv.z * s0.z + wv.w * s0.w;
                    a1 += wv.x * s1.x + wv.y * s1.y + wv.z * s1.z + wv.w * s1.w;
                    a2 += wv.x * s2.x + wv.y * s2.y + wv.z * s2.z + wv.w * s2.w;
                    a3 += wv.x * s3.x + wv.y * s3.y + wv.z * s3.z + wv.w * s3.w;
                }
                sSW[0 * SST + f_] = a0;
                sSW[1 * SST + f_] = a1;
                sSW[2 * SST + f_] = a2;
                sSW[3 * SST + f_] = a3;
            } else if (i < 180) {
                // gate: z = inv*(h.s) + wm.s  (h.s from fused epilogue dots)
                int row = i - 100;
                int bi = row / N_, ne = row % N_;
                const float* wp = sWm + ne * SST;
                const float* sp = sScur + bi * SST;
                float ws = 0.f;
                for (int e4 = 0; e4 < 25; e4++) {
                    float4 wv = *(const float4*)(wp + e4 * 4);
                    float4 sv = *(const float4*)(sp + e4 * 4);
                    ws += wv.x * sv.x + wv.y * sv.y + wv.z * sv.z + wv.w * sv.w;
                }
                float inv = rsqrtf(sGp[2 * row] + sGp[2 * row + 1]);
                float z = inv * (sDot[2 * row] + sDot[2 * row + 1]) + ws;
                sG[row] = 1.f / (1.f + expf(-z));
            }
            // combine + store s_{t+1} (end of phase A; LDG latency covered)
            if (t + 1 < NCH) {
                float* sNxt = sS + ((t + 1) & 1) * NB * SST;
                int bi0 = pf0 / E_, e0 = pf0 % E_;
                int bi1 = pf1 / E_, e1 = pf1 % E_;
                float a = 0.f, b = 0.f;
#pragma unroll
                for (int l = 0; l < L_; l++) a += sF[l * E_ + e0] * v0[l];
#pragma unroll
                for (int l = 0; l < L_; l++) b += sF[l * E_ + e1] * v1[l];
                sNxt[bi0 * SST + e0] = a;
                sNxt[bi1 * SST + e1] = b;
                if (pfh2) {
                    int bi2 = pf2 / E_, e2 = pf2 % E_;
                    float c = 0.f;
#pragma unroll
                    for (int l = 0; l < L_; l++) c += sF[l * E_ + e2] * v2[l];
                    sNxt[bi2 * SST + e2] = c;
                }
            }
        }
        __syncthreads();

        // ================= phase B: epilogue + A-tile store + gate dot ====
        if (w < 10) {
            const float* sNext = sS + ((t + 1) & 1) * NB * SST;
            float g0 = sG[r0], g1 = sG[r1];
            int bi0 = r0 / N_, ne0 = r0 % N_;
            int bi1 = r1 / N_, ne1 = r1 % N_;
            float ssq0 = 0.f, ssq1 = 0.f;
            float dot0 = 0.f, dot1 = 0.f;
#pragma unroll
            for (int j = 0; j < 7; j++) {
                int f0 = (nh * 7 + j) * 8 + 2 * qc;
                if (f0 < 100) {
                    float2 vw0 = *(const float2*)(sVw + ne0 * SST + f0);
                    float2 sw0 = *(const float2*)(sSW + bi0 * SST + f0);
                    float c0 = acc[j][0] * inv0 + vw0.x + sw0.x;
                    float c1 = acc[j][1] * inv0 + vw0.y + sw0.y;
                    c0 = (c0 >= 0.f) ? c0 : adm * c0;
                    c1 = (c1 >= 0.f) ? c1 : adm * c1;
                    float n0v = hreg[j][0] * inv0 + g0 * c0;
                    float n1v = hreg[j][1] * inv0 + g0 * c1;
                    hreg[j][0] = n0v; hreg[j][1] = n1v;
                    ssq0 += n0v * n0v + n1v * n1v;
                    float2 sn0 = *(const float2*)(sNext + bi0 * SST + f0);
                    dot0 += n0v * sn0.x + n1v * sn0.y;
                    *(uint32_t*)(smc + OFF_AHI + r0 * BST + f0 * 2) = pack_h2(n0v, n1v);

                    float2 vw1 = *(const float2*)(sVw + ne1 * SST + f0);
                    float2 sw1 = *(const float2*)(sSW + bi1 * SST + f0);
                    float d0 = acc[j][2] * inv1 + vw1.x + sw1.x;
                    float d1 = acc[j][3] * inv1 + vw1.y + sw1.y;
                    d0 = (d0 >= 0.f) ? d0 : adm * d0;
                    d1 = (d1 >= 0.f) ? d1 : adm * d1;
                    float m0v = hreg[j][2] * inv1 + g1 * d0;
                    float m1v = hreg[j][3] * inv1 + g1 * d1;
                    hreg[j][2] = m0v; hreg[j][3] = m1v;
                    ssq1 += m0v * m0v + m1v * m1v;
                    float2 sn1 = *(const float2*)(sNext + bi1 * SST + f0);
                    dot1 += m0v * sn1.x + m1v * sn1.y;
                    *(uint32_t*)(smc + OFF_AHI + r1 * BST + f0 * 2) = pack_h2(m0v, m1v);
                }
            }
            ssq0 += __shfl_xor_sync(0xffffffffu, ssq0, 1);
            ssq0 += __shfl_xor_sync(0xffffffffu, ssq0, 2);
            ssq1 += __shfl_xor_sync(0xffffffffu, ssq1, 1);
            ssq1 += __shfl_xor_sync(0xffffffffu, ssq1, 2);
            dot0 += __shfl_xor_sync(0xffffffffu, dot0, 1);
            dot0 += __shfl_xor_sync(0xffffffffu, dot0, 2);
            dot1 += __shfl_xor_sync(0xffffffffu, dot1, 1);
            dot1 += __shfl_xor_sync(0xffffffffu, dot1, 2);
            if (qc == 0) {
                sGp[2 * r0 + nh] = ssq0;
                sGp[2 * r1 + nh] = ssq1;
                sDot[2 * r0 + nh] = dot0;
                sDot[2 * r1 + nh] = dot1;
            }
        }
        __syncthreads();
    }

    // ---- write register h back to sH for the fused tail ----
    if (w < 10) {
#pragma unroll
        for (int j = 0; j < 7; j++) {
            int f0 = (nh * 7 + j) * 8 + 2 * qc;
            if (f0 < 100) {
                *(float2*)(sH + r0 * HST + f0) = make_float2(hreg[j][0], hreg[j][1]);
                *(float2*)(sH + r1 * HST + f0) = make_float2(hreg[j][2], hreg[j][3]);
            }
        }
    }
    if (tid < 80) sG[tid] = rsqrtf(sGp[2 * tid] + sGp[2 * tid + 1]);
    __syncthreads();

    // ================= fused attention + head ==========================
    for (int i = tid; i < 80 * E_; i += NTH) {
        int row = i / E_, e_ = i % E_;
        sH[row * HST + e_] *= sG[row];
    }
    {
        float* sQ = sS;
        for (int i = tid; i < NB * E_; i += NTH) {
            int bi = i / E_, e_ = i % E_;
            const float* ip = in_data + ((long)(b0g + bi) * T_ + NCH * L_) * E_ + e_;
            float acc = 0.f;
#pragma unroll
            for (int l = 0; l < REST; l++) acc += sF[l * E_ + e_] * ip[(long)l * E_];
            sQ[bi * SST + e_] = acc;
        }
    }
    for (int i = tid; i < E_ * E_; i += NTH) sW[i] = H_w[i];
    __syncthreads();
    if (tid < 80) {
        int bi = tid / N_;
        const float* hp = sH + tid * HST;
        const float* qp = sS + bi * SST;
        float d = 0.f;
        for (int e4 = 0; e4 < 25; e4++) {
            float4 hv = *(const float4*)(hp + e4 * 4);
            float4 qv = *(const float4*)(qp + e4 * 4);
            d += hv.x * qv.x + hv.y * qv.y + hv.z * qv.z + hv.w * qv.w;
        }
        sGp[tid] = d;
    }
    __syncthreads();
    if (tid < NB) {
        const float* lp = sGp + tid * N_;
        float m = lp[0];
        for (int n = 1; n < N_; n++) m = fmaxf(m, lp[n]);
        float s = 0.f;
        float* pp = sG + tid * N_;
        for (int n = 0; n < N_; n++) { float ev = expf(lp[n] - m); pp[n] = ev; s += ev; }
        float inv = 1.f / s;
        for (int n = 0; n < N_; n++) pp[n] *= inv;
    }
    __syncthreads();
    {
        float* sU = sS + NB * SST;
        for (int i = tid; i < NB * E_; i += NTH) {
            int bi = i / E_, e_ = i % E_;
            float u = 0.f;
#pragma unroll
            for (int n = 0; n < N_; n++) u += sG[bi * N_ + n] * sH[(bi * N_ + n) * HST + e_];
            sU[bi * SST + e_] = u;
        }
    }
    __syncthreads();
    {
        const float* sQ = sS;
        const float* sU = sS + NB * SST;
        float ao = *a_out_p;
        for (int i = tid; i < NB * E_; i += NTH) {
            int bi = i / E_, f_ = i % E_;
            float acc = sQ[bi * SST + f_] + H_b[f_];
            const float* hw = sW + f_ * E_;
            const float* up = sU + bi * SST;
            for (int e4 = 0; e4 < 25; e4++) {
                float4 hv = *(const float4*)(hw + e4 * 4);
                float4 uv = *(const float4*)(up + e4 * 4);
                acc += hv.x * uv.x + hv.y * uv.y + hv.z * uv.z + hv.w * uv.w;
            }
            g_ya[(long)(b0g + bi) * E_ + f_] = (acc >= 0.f) ? acc : ao * acc;
        }
    }
}

// ============================================================
// K3: convert R_w and g_ya into packed bf16 hi/lo pair rows
// ============================================================
__global__ void convert_kernel(const float* __restrict__ R_w) {
    int idx = blockIdx.x * 256 + threadIdx.x;
    const int RTOT = V_ * 60;
    if (idx < RTOT) {
        int v = idx / 60, p = idx % 60;
        uint32_t hi = 0, lo = 0;
        if (p < 50) {
            float2 rv = *(const float2*)(R_w + (long)v * E_ + 2 * p);
            split2(rv.x, rv.y, hi, lo);
        }
        g_Rhi[idx] = hi;
        g_Rlo[idx] = lo;
    } else if (idx < RTOT + B_ * 60) {
        int i = idx - RTOT;
        int b = i / 60, p = i % 60;
        uint32_t hi = 0, lo = 0;
        if (p < 50) {
            float2 yv = *(const float2*)(g_ya + (long)b * E_ + 2 * p);
            split2(yv.x, yv.y, hi, lo);
        }
        g_Yhi[i] = hi;
        g_Ylo[i] = lo;
    }
}

// ============================================================
// K4: out = ya @ R_w^T + R_b on HMMA (bf16x3). 128b x 128v tiles.
// ============================================================
#define O_AHI 0
#define O_ALO 30720
#define O_BHI 61440
#define O_BLO 92160
#define OUT_SMEM 122880

__global__ __launch_bounds__(256, 1) void out_mma_kernel(
    const float* __restrict__ R_b, float* __restrict__ out)
{
    extern __shared__ char smo[];
    const int tid = threadIdx.x;
    const int w = tid >> 5;
    const int lane = tid & 31;
    const int v0 = blockIdx.x * 128;
    const int b0 = blockIdx.y * 128;
    const uint32_t smb = smem_u32(smo);

    uint32_t* sAhi = (uint32_t*)(smo + O_AHI);
    uint32_t* sAlo = (uint32_t*)(smo + O_ALO);
    uint32_t* sBhi = (uint32_t*)(smo + O_BHI);
    uint32_t* sBlo = (uint32_t*)(smo + O_BLO);
    for (int i = tid; i < 128 * 60; i += 256) {
        int r = i / 60, p = i % 60;
        sAhi[i] = g_Yhi[(b0 + r) * 60 + p];
        sAlo[i] = g_Ylo[(b0 + r) * 60 + p];
        sBhi[i] = g_Rhi[(long)(v0 + r) * 60 + p];
        sBlo[i] = g_Rlo[(long)(v0 + r) * 60 + p];
    }
    __syncthreads();

    const int mw = w >> 1, nw = w & 1;
    const int m0 = mw * 32;
    const int n0 = nw * 64;
    const int qr = lane >> 2, qc = lane & 3;
    const int grp = lane >> 3, lr = lane & 7;

    float acc[2][8][4];
#pragma unroll
    for (int mh = 0; mh < 2; mh++)
#pragma unroll
        for (int j = 0; j < 8; j++)
#pragma unroll
            for (int q = 0; q < 4; q++) acc[mh][j][q] = 0.f;

#pragma unroll
    for (int k = 0; k < 7; k++) {
        uint32_t ah[2][4], al[2][4];
#pragma unroll
        for (int mh = 0; mh < 2; mh++) {
            uint32_t aaddr = smb + O_AHI + (uint32_t)((m0 + 16 * mh + lr + ((grp & 1) << 3)) * 240
                           + k * 32 + ((grp >> 1) << 4));
            ldsm4(ah[mh], aaddr);
            ldsm4(al[mh], aaddr + 30720u);
        }
#pragma unroll
        for (int pq = 0; pq < 4; pq++) {
            uint32_t addr = smb + O_BHI + (uint32_t)((n0 + pq * 16 + lr + (grp >> 1) * 8) * 240
                          + k * 32 + (grp & 1) * 16);
            uint32_t bh[4], bl[4];
            ldsm4(bh, addr);
            ldsm4(bl, addr + 30720u);
#pragma unroll
            for (int mh = 0; mh < 2; mh++)
#pragma unroll
                for (int jj = 0; jj < 2; jj++) {
                    int j = pq * 2 + jj;
                    mma16816(acc[mh][j], ah[mh], &bh[2 * jj]);
                    mma16816(acc[mh][j], al[mh], &bh[2 * jj]);
                    mma16816(acc[mh][j], ah[mh], &bl[2 * jj]);
                }
        }
    }

#pragma unroll
    for (int mh = 0; mh < 2; mh++) {
        int ra = b0 + m0 + 16 * mh + qr;
        int rb2 = ra + 8;
#pragma unroll
        for (int j = 0; j < 8; j++) {
            int c = v0 + n0 + j * 8 + 2 * qc;
            float2 rb = *(const float2*)(R_b + c);
            float2 o0 = make_float2(acc[mh][j][0] + rb.x, acc[mh][j][1] + rb.y);
            float2 o1 = make_float2(acc[mh][j][2] + rb.x, acc[mh][j][3] + rb.y);
            *(float2*)(out + (long)ra * V_ + c) = o0;
            *(float2*)(out + (long)rb2 * V_ + c) = o1;
        }
    }
}

// ============================================================
extern "C" void kernel_launch(void* const* d_in, const int* in_sizes, int n_in,
                              void* d_out, int out_size) {
    const float* in_data = (const float*)d_in[0];
    const float* f       = (const float*)d_in[1];
    const float* h0      = (const float*)d_in[2];
    const float* w_mem   = (const float*)d_in[3];
    const float* U_w     = (const float*)d_in[4];
    const float* V_w     = (const float*)d_in[5];
    const float* W_w     = (const float*)d_in[6];
    const float* a_dm    = (const float*)d_in[7];
    const float* H_w     = (const float*)d_in[8];
    const float* H_b     = (const float*)d_in[9];
    const float* R_w     = (const float*)d_in[10];
    const float* R_b     = (const float*)d_in[11];
    const float* a_out   = (const float*)d_in[12];
    float* out = (float*)d_out;

    cudaFuncSetAttribute(scan_mma_kernel, cudaFuncAttributeMaxDynamicSharedMemorySize,
                         SCAN_SMEM);
    cudaFuncSetAttribute(out_mma_kernel, cudaFuncAttributeMaxDynamicSharedMemorySize,
                         OUT_SMEM);

    scan_mma_kernel<<<B_ / NB, NTH, SCAN_SMEM>>>(U_w, V_w, W_w, w_mem, h0, a_dm,
                                                 in_data, f, H_w, H_b, a_out);
    const int conv_total = V_ * 60 + B_ * 60;
    convert_kernel<<<(conv_total + 255) / 256, 256>>>(R_w);
    dim3 g4(V_ / 128, B_ / 128);
    out_mma_kernel<<<g4, 256, OUT_SMEM>>>(R_b, out);
}

// round 17
// speedup vs baseline: 1.3478x; 1.0035x over previous
#include <cuda_runtime.h>
#include <cuda_bf16.h>
#include <cuda_fp16.h>
#include <math.h>
#include <stdint.h>

#define B_   512
#define T_   1005
#define E_   100
#define L_   10
#define N_   20
#define V_   32000
#define NCH  100      // n_full = T/L
#define REST 5        // T % L

// ---- scratch (no allocations allowed) ----
__device__ float g_ya[B_ * E_];                 // prelu(y)
__device__ uint32_t g_Rhi[V_ * 60];             // R_w bf16-hi pairs, 240B rows
__device__ uint32_t g_Rlo[V_ * 60];
__device__ uint32_t g_Yhi[B_ * 60];             // ya bf16-hi pairs
__device__ uint32_t g_Ylo[B_ * 60];

// ---- warp MMA helpers (portable PTX, sm_80+) ----
__device__ __forceinline__ uint32_t smem_u32(const void* p) {
    uint32_t a;
    asm("{ .reg .u64 t; cvta.to.shared.u64 t, %1; cvt.u32.u64 %0, t; }"
        : "=r"(a) : "l"(p));
    return a;
}
__device__ __forceinline__ void ldsm4(uint32_t* r, uint32_t a) {
    asm volatile("ldmatrix.sync.aligned.m8n8.x4.shared.b16 {%0,%1,%2,%3}, [%4];"
        : "=r"(r[0]), "=r"(r[1]), "=r"(r[2]), "=r"(r[3]) : "r"(a));
}
__device__ __forceinline__ void ldsm2(uint32_t* r, uint32_t a) {
    asm volatile("ldmatrix.sync.aligned.m8n8.x2.shared.b16 {%0,%1}, [%2];"
        : "=r"(r[0]), "=r"(r[1]) : "r"(a));
}
// bf16 MMA (out GEMM)
__device__ __forceinline__ void mma16816(float* c, const uint32_t* a, const uint32_t* b) {
    asm volatile(
        "mma.sync.aligned.m16n8k16.row.col.f32.bf16.bf16.f32 "
        "{%0,%1,%2,%3}, {%4,%5,%6,%7}, {%8,%9}, {%0,%1,%2,%3};"
        : "+f"(c[0]), "+f"(c[1]), "+f"(c[2]), "+f"(c[3])
        : "r"(a[0]), "r"(a[1]), "r"(a[2]), "r"(a[3]), "r"(b[0]), "r"(b[1]));
}
// fp16 MMA (scan GEMM)
__device__ __forceinline__ void mma16816h(float* c, const uint32_t* a, const uint32_t* b) {
    asm volatile(
        "mma.sync.aligned.m16n8k16.row.col.f32.f16.f16.f32 "
        "{%0,%1,%2,%3}, {%4,%5,%6,%7}, {%8,%9}, {%0,%1,%2,%3};"
        : "+f"(c[0]), "+f"(c[1]), "+f"(c[2]), "+f"(c[3])
        : "r"(a[0]), "r"(a[1]), "r"(a[2]), "r"(a[3]), "r"(b[0]), "r"(b[1]));
}
// split two fp32 into packed bf16 hi + residual lo (out GEMM convert)
__device__ __forceinline__ void split2(float x0, float x1, uint32_t& hi, uint32_t& lo) {
    __nv_bfloat162 bh = __floats2bfloat162_rn(x0, x1);
    uint32_t h = *reinterpret_cast<uint32_t*>(&bh);
    float hf0 = __uint_as_float(h << 16);
    float hf1 = __uint_as_float(h & 0xffff0000u);
    __nv_bfloat162 bl = __floats2bfloat162_rn(x0 - hf0, x1 - hf1);
    hi = h;
    lo = *reinterpret_cast<uint32_t*>(&bl);
}
// pack two fp32 into fp16x2
__device__ __forceinline__ uint32_t pack_h2(float x0, float x1) {
    __half2 h2 = __floats2half2_rn(x0, x1);
    return *reinterpret_cast<uint32_t*>(&h2);
}

// ============================================================
// K2: persistent scan on warp MMA (plain fp16 HMMA).
//     128 CTAs x 4 batches; 10 MMA + 6 helper warps.
//     h register-resident; gate dot fused; sSW double-buffered
//     and computed in phase B (helpers' idle slot).
// ============================================================
#define NB   4
#define NTH  512
#define BST  240
#define HST  108
#define SST  104

#define OFF_AHI 0                          // 19200
#define OFF_BHI 19200                      // 26880 -> 46080
#define OFF_H   46080                      // 34560 -> 80640
#define OFF_W   80640                      // 40000 -> 120640
#define OFF_WM  120640                     // 8320 -> 128960
#define OFF_VW  128960                     // 8320 -> 137280
#define OFF_S   137280                     // 3328 -> 140608
#define OFF_SSW 140608                     // 2*1664 = 3328 -> 143936
#define OFF_G   143936                     // 320 -> 144256
#define OFF_GP  144256                     // 640 -> 144896
#define OFF_F   144896                     // 4000 -> 148896
#define OFF_DOT 148896                     // 640 -> 149536
#define SCAN_SMEM 149536

__global__ __launch_bounds__(NTH, 1) void scan_mma_kernel(
    const float* __restrict__ U_w, const float* __restrict__ V_w,
    const float* __restrict__ W_w, const float* __restrict__ w_mem,
    const float* __restrict__ h0,  const float* __restrict__ a_dm_p,
    const float* __restrict__ in_data, const float* __restrict__ f_w,
    const float* __restrict__ H_w, const float* __restrict__ H_b,
    const float* __restrict__ a_out_p)
{
    extern __shared__ char smc[];
    float* sH  = (float*)(smc + OFF_H);
    float* sW  = (float*)(smc + OFF_W);
    float* sWm = (float*)(smc + OFF_WM);
    float* sVw = (float*)(smc + OFF_VW);
    float* sS  = (float*)(smc + OFF_S);
    float* sSWb= (float*)(smc + OFF_SSW);   // 2 buffers of NB*SST
    float* sG  = (float*)(smc + OFF_G);
    float* sGp = (float*)(smc + OFF_GP);
    float* sF  = (float*)(smc + OFF_F);
    float* sDot= (float*)(smc + OFF_DOT);

    const int tid = threadIdx.x;
    const int w = tid >> 5;
    const int lane = tid & 31;
    const int b0g = blockIdx.x * NB;
    const float adm = *a_dm_p;
    const uint32_t smb = smem_u32(smc);

    // ---- zero A+B tiles (pad rows/cols must stay zero) ----
    for (int i = tid; i < OFF_H / 4; i += NTH) ((uint32_t*)smc)[i] = 0;
    __syncthreads();

    // ---- stage U (fp16), W, w_mem, f, h init + A tile from h0 ----
    for (int i = tid; i < E_ * 50; i += NTH) {
        int f_ = i / 50, p = i % 50;
        float2 uv = *(const float2*)(U_w + f_ * E_ + 2 * p);
        *(uint32_t*)(smc + OFF_BHI + f_ * BST + p * 4) = pack_h2(uv.x, uv.y);
    }
    for (int i = tid; i < E_ * E_; i += NTH) sW[i] = W_w[i];
    for (int i = tid; i < L_ * E_; i += NTH) sF[i] = f_w[i];
    for (int i = tid; i < N_ * E_; i += NTH) {
        int n_ = i / E_, e_ = i % E_;
        sWm[n_ * SST + e_] = w_mem[i];
    }
    for (int i = tid; i < 80 * 50; i += NTH) {
        int row = i / 50, p = i % 50;
        float2 hv = *(const float2*)(h0 + (row % N_) * E_ + 2 * p);
        *(float2*)(sH + row * HST + 2 * p) = hv;
        *(uint32_t*)(smc + OFF_AHI + row * BST + p * 4) = pack_h2(hv.x, hv.y);
    }
    if (tid < 80) { sGp[2 * tid] = 1.f; sGp[2 * tid + 1] = 0.f; }
    __syncthreads();
    // Vw[n][f] = w_mem[n] . V_w[f] (one-time)
    for (int i = tid; i < N_ * E_; i += NTH) {
        int n_ = i / E_, f_ = i % E_;
        float acc = 0.f;
        for (int e_ = 0; e_ < E_; e_++) acc += sWm[n_ * SST + e_] * V_w[f_ * E_ + e_];
        sVw[n_ * SST + f_] = acc;
    }
    // s_0 = infos(t=0)
    for (int i = tid; i < NB * E_; i += NTH) {
        int bi = i / E_, e_ = i % E_;
        const float* ip = in_data + (long)(b0g + bi) * T_ * E_ + e_;
        float acc = 0.f;
#pragma unroll
        for (int l = 0; l < L_; l++) acc += sF[l * E_ + e_] * ip[(long)l * E_];
        sS[bi * SST + e_] = acc;
    }
    __syncthreads();
    // sDot init (h0 . s0) and SSW(0) prologue
    for (int r = tid; r < 80; r += NTH) {
        const float* hp = sH + r * HST;
        const float* sp = sS + (r / N_) * SST;
        float d = 0.f;
        for (int e4 = 0; e4 < 25; e4++) {
            float4 hv = *(const float4*)(hp + e4 * 4);
            float4 sv = *(const float4*)(sp + e4 * 4);
            d += hv.x * sv.x + hv.y * sv.y + hv.z * sv.z + hv.w * sv.w;
        }
        sDot[2 * r] = d;
        sDot[2 * r + 1] = 0.f;
    }
    for (int f_ = tid; f_ < E_; f_ += NTH) {
        float a0 = 0.f, a1 = 0.f, a2 = 0.f, a3 = 0.f;
        const float* wp = sW + f_ * E_;
        for (int e4 = 0; e4 < 25; e4++) {
            float4 wv = *(const float4*)(wp + e4 * 4);
            float4 s0 = *(const float4*)(sS + 0 * SST + e4 * 4);
            float4 s1 = *(const float4*)(sS + 1 * SST + e4 * 4);
            float4 s2 = *(const float4*)(sS + 2 * SST + e4 * 4);
            float4 s3 = *(const float4*)(sS + 3 * SST + e4 * 4);
            a0 += wv.x * s0.x + wv.y * s0.y + wv.z * s0.z + wv.w * s0.w;
            a1 += wv.x * s1.x + wv.y * s1.y + wv.z * s1.z + wv.w * s1.w;
            a2 += wv.x * s2.x + wv.y * s2.y + wv.z * s2.z + wv.w * s2.w;
            a3 += wv.x * s3.x + wv.y * s3.y + wv.z * s3.z + wv.w * s3.w;
        }
        sSWb[0 * SST + f_] = a0;
        sSWb[1 * SST + f_] = a1;
        sSWb[2 * SST + f_] = a2;
        sSWb[3 * SST + f_] = a3;
    }
    __syncthreads();

    const int stripe = w >> 1, nh = w & 1;
    const int m0 = stripe * 16;
    const int qr = lane >> 2, qc = lane & 3;
    const int r0 = m0 + qr, r1 = r0 + 8;
    const int grp = lane >> 3, lr = lane & 7;

    const int pf0 = tid - 320;
    const int pf1 = pf0 + 192;
    const int pf2 = pf0 + 384;
    const bool pfh2 = (pf0 >= 0) && (pf2 < NB * E_);

    // ---- h register-resident in MMA threads ----
    float hreg[7][4];
    if (w < 10) {
#pragma unroll
        for (int j = 0; j < 7; j++) {
            int f0 = (nh * 7 + j) * 8 + 2 * qc;
            if (f0 < 100) {
                float2 a = *(const float2*)(sH + r0 * HST + f0);
                float2 b = *(const float2*)(sH + r1 * HST + f0);
                hreg[j][0] = a.x; hreg[j][1] = a.y;
                hreg[j][2] = b.x; hreg[j][3] = b.y;
            }
        }
    }

    for (int t = 0; t < NCH; t++) {
        float acc[7][4];
        float inv0 = 0.f, inv1 = 0.f;

        // ================= phase A: fp16 MMA | gate + s-prefetch ==========
        if (w < 10) {
            inv0 = rsqrtf(sGp[2 * r0] + sGp[2 * r0 + 1]);
            inv1 = rsqrtf(sGp[2 * r1] + sGp[2 * r1 + 1]);
#pragma unroll
            for (int j = 0; j < 7; j++)
#pragma unroll
                for (int q = 0; q < 4; q++) acc[j][q] = 0.f;
            const uint32_t aBase = smb + OFF_AHI;
            const uint32_t bhBase = smb + OFF_BHI;
#pragma unroll
            for (int k = 0; k < 7; k++) {
                uint32_t ah[4];
                uint32_t aaddr = aBase + (uint32_t)((m0 + lr + ((grp & 1) << 3)) * BST
                               + k * 32 + ((grp >> 1) << 4));
                ldsm4(ah, aaddr);
                uint32_t bh[14];
#pragma unroll
                for (int pq = 0; pq < 3; pq++) {
                    int t0 = nh * 7 + pq * 2;
                    uint32_t addr = bhBase + (uint32_t)((t0 * 8 + lr + (grp >> 1) * 8) * BST
                                  + k * 32 + (grp & 1) * 16);
                    ldsm4(&bh[pq * 4], addr);
                }
#pragma unroll
                for (int j = 0; j < 6; j++) {
                    mma16816h(acc[j], ah, &bh[2 * j]);
                }
                if (nh == 0) {   // tail tile j=6 (cols 48-55)
                    uint32_t addr = bhBase + (uint32_t)((6 * 8 + lr) * BST
                                  + k * 32 + ((lane >> 3) & 1) * 16);
                    uint32_t bht[2];
                    ldsm2(bht, addr);
                    mma16816h(acc[6], ah, bht);
                }
            }
        } else {
            const float* sScur = sS + (t & 1) * NB * SST;
            float v0[10], v1[10], v2[10];
            if (t + 1 < NCH) {
                int bi0 = pf0 / E_, e0 = pf0 % E_;
                int bi1 = pf1 / E_, e1 = pf1 % E_;
                const float* ip0 = in_data + ((long)(b0g + bi0) * T_ + (t + 1) * L_) * E_ + e0;
                const float* ip1 = in_data + ((long)(b0g + bi1) * T_ + (t + 1) * L_) * E_ + e1;
#pragma unroll
                for (int l = 0; l < L_; l++) v0[l] = ip0[(long)l * E_];
#pragma unroll
                for (int l = 0; l < L_; l++) v1[l] = ip1[(long)l * E_];
                if (pfh2) {
                    int bi2 = pf2 / E_, e2 = pf2 % E_;
                    const float* ip2 = in_data + ((long)(b0g + bi2) * T_ + (t + 1) * L_) * E_ + e2;
#pragma unroll
                    for (int l = 0; l < L_; l++) v2[l] = ip2[(long)l * E_];
                }
            }
            // gate: z = inv*(h.s) + wm.s  (h.s from fused epilogue dots)
            if (pf0 < 80) {
                int row = pf0;
                int bi = row / N_, ne = row % N_;
                const float* wp = sWm + ne * SST;
                const float* sp = sScur + bi * SST;
                float ws = 0.f;
                for (int e4 = 0; e4 < 25; e4++) {
                    float4 wv = *(const float4*)(wp + e4 * 4);
                    float4 sv = *(const float4*)(sp + e4 * 4);
                    ws += wv.x * sv.x + wv.y * sv.y + wv.z * sv.z + wv.w * sv.w;
                }
                float inv = rsqrtf(sGp[2 * row] + sGp[2 * row + 1]);
                float z = inv * (sDot[2 * row] + sDot[2 * row + 1]) + ws;
                sG[row] = 1.f / (1.f + expf(-z));
            }
            // combine + store s_{t+1}
            if (t + 1 < NCH) {
                float* sNxt = sS + ((t + 1) & 1) * NB * SST;
                int bi0 = pf0 / E_, e0 = pf0 % E_;
                int bi1 = pf1 / E_, e1 = pf1 % E_;
                float a = 0.f, b = 0.f;
#pragma unroll
                for (int l = 0; l < L_; l++) a += sF[l * E_ + e0] * v0[l];
#pragma unroll
                for (int l = 0; l < L_; l++) b += sF[l * E_ + e1] * v1[l];
                sNxt[bi0 * SST + e0] = a;
                sNxt[bi1 * SST + e1] = b;
                if (pfh2) {
                    int bi2 = pf2 / E_, e2 = pf2 % E_;
                    float c = 0.f;
#pragma unroll
                    for (int l = 0; l < L_; l++) c += sF[l * E_ + e2] * v2[l];
                    sNxt[bi2 * SST + e2] = c;
                }
            }
        }
        __syncthreads();

        // ===== phase B: epilogue + A-store + gate dot | SSW(t+1) ==========
        if (w < 10) {
            const float* sSWc = sSWb + (t & 1) * NB * SST;
            const float* sNext = sS + ((t + 1) & 1) * NB * SST;
            float g0 = sG[r0], g1 = sG[r1];
            int bi0 = r0 / N_, ne0 = r0 % N_;
            int bi1 = r1 / N_, ne1 = r1 % N_;
            float ssq0 = 0.f, ssq1 = 0.f;
            float dot0 = 0.f, dot1 = 0.f;
#pragma unroll
            for (int j = 0; j < 7; j++) {
                int f0 = (nh * 7 + j) * 8 + 2 * qc;
                if (f0 < 100) {
                    float2 vw0 = *(const float2*)(sVw + ne0 * SST + f0);
                    float2 sw0 = *(const float2*)(sSWc + bi0 * SST + f0);
                    float c0 = acc[j][0] * inv0 + vw0.x + sw0.x;
                    float c1 = acc[j][1] * inv0 + vw0.y + sw0.y;
                    c0 = (c0 >= 0.f) ? c0 : adm * c0;
                    c1 = (c1 >= 0.f) ? c1 : adm * c1;
                    float n0v = hreg[j][0] * inv0 + g0 * c0;
                    float n1v = hreg[j][1] * inv0 + g0 * c1;
                    hreg[j][0] = n0v; hreg[j][1] = n1v;
                    ssq0 += n0v * n0v + n1v * n1v;
                    float2 sn0 = *(const float2*)(sNext + bi0 * SST + f0);
                    dot0 += n0v * sn0.x + n1v * sn0.y;
                    *(uint32_t*)(smc + OFF_AHI + r0 * BST + f0 * 2) = pack_h2(n0v, n1v);

                    float2 vw1 = *(const float2*)(sVw + ne1 * SST + f0);
                    float2 sw1 = *(const float2*)(sSWc + bi1 * SST + f0);
                    float d0 = acc[j][2] * inv1 + vw1.x + sw1.x;
                    float d1 = acc[j][3] * inv1 + vw1.y + sw1.y;
                    d0 = (d0 >= 0.f) ? d0 : adm * d0;
                    d1 = (d1 >= 0.f) ? d1 : adm * d1;
                    float m0v = hreg[j][2] * inv1 + g1 * d0;
                    float m1v = hreg[j][3] * inv1 + g1 * d1;
                    hreg[j][2] = m0v; hreg[j][3] = m1v;
                    ssq1 += m0v * m0v + m1v * m1v;
                    float2 sn1 = *(const float2*)(sNext + bi1 * SST + f0);
                    dot1 += m0v * sn1.x + m1v * sn1.y;
                    *(uint32_t*)(smc + OFF_AHI + r1 * BST + f0 * 2) = pack_h2(m0v, m1v);
                }
            }
            ssq0 += __shfl_xor_sync(0xffffffffu, ssq0, 1);
            ssq0 += __shfl_xor_sync(0xffffffffu, ssq0, 2);
            ssq1 += __shfl_xor_sync(0xffffffffu, ssq1, 1);
            ssq1 += __shfl_xor_sync(0xffffffffu, ssq1, 2);
            dot0 += __shfl_xor_sync(0xffffffffu, dot0, 1);
            dot0 += __shfl_xor_sync(0xffffffffu, dot0, 2);
            dot1 += __shfl_xor_sync(0xffffffffu, dot1, 1);
            dot1 += __shfl_xor_sync(0xffffffffu, dot1, 2);
            if (qc == 0) {
                sGp[2 * r0 + nh] = ssq0;
                sGp[2 * r1 + nh] = ssq1;
                sDot[2 * r0 + nh] = dot0;
                sDot[2 * r1 + nh] = dot1;
            }
        } else if (t + 1 < NCH && pf0 < 100) {
            // SSW(t+1): sSW[(t+1)&1][bi][f] = s_{t+1}[bi] . W[f]
            const float* sNew = sS + ((t + 1) & 1) * NB * SST;
            float* sSWn = sSWb + ((t + 1) & 1) * NB * SST;
            int f_ = pf0;
            float a0 = 0.f, a1 = 0.f, a2 = 0.f, a3 = 0.f;
            const float* wp = sW + f_ * E_;
            for (int e4 = 0; e4 < 25; e4++) {
                float4 wv = *(const float4*)(wp + e4 * 4);
                float4 s0 = *(const float4*)(sNew + 0 * SST + e4 * 4);
                float4 s1 = *(const float4*)(sNew + 1 * SST + e4 * 4);
                float4 s2 = *(const float4*)(sNew + 2 * SST + e4 * 4);
                float4 s3 = *(const float4*)(sNew + 3 * SST + e4 * 4);
                a0 += wv.x * s0.x + wv.y * s0.y + wv.z * s0.z + wv.w * s0.w;
                a1 += wv.x * s1.x + wv.y * s1.y + wv.z * s1.z + wv.w * s1.w;
                a2 += wv.x * s2.x + wv.y * s2.y + wv.z * s2.z + wv.w * s2.w;
                a3 += wv.x * s3.x + wv.y * s3.y + wv.z * s3.z + wv.w * s3.w;
            }
            sSWn[0 * SST + f_] = a0;
            sSWn[1 * SST + f_] = a1;
            sSWn[2 * SST + f_] = a2;
            sSWn[3 * SST + f_] = a3;
        }
        __syncthreads();
    }

    // ---- write register h back to sH for the fused tail ----
    if (w < 10) {
#pragma unroll
        for (int j = 0; j < 7; j++) {
            int f0 = (nh * 7 + j) * 8 + 2 * qc;
            if (f0 < 100) {
                *(float2*)(sH + r0 * HST + f0) = make_float2(hreg[j][0], hreg[j][1]);
                *(float2*)(sH + r1 * HST + f0) = make_float2(hreg[j][2], hreg[j][3]);
            }
        }
    }
    if (tid < 80) sG[tid] = rsqrtf(sGp[2 * tid] + sGp[2 * tid + 1]);
    __syncthreads();

    // ================= fused attention + head ==========================
    for (int i = tid; i < 80 * E_; i += NTH) {
        int row = i / E_, e_ = i % E_;
        sH[row * HST + e_] *= sG[row];
    }
    {
        float* sQ = sS;
        for (int i = tid; i < NB * E_; i += NTH) {
            int bi = i / E_, e_ = i % E_;
            const float* ip = in_data + ((long)(b0g + bi) * T_ + NCH * L_) * E_ + e_;
            float acc = 0.f;
#pragma unroll
            for (int l = 0; l < REST; l++) acc += sF[l * E_ + e_] * ip[(long)l * E_];
            sQ[bi * SST + e_] = acc;
        }
    }
    for (int i = tid; i < E_ * E_; i += NTH) sW[i] = H_w[i];
    __syncthreads();
    if (tid < 80) {
        int bi = tid / N_;
        const float* hp = sH + tid * HST;
        const float* qp = sS + bi * SST;
        float d = 0.f;
        for (int e4 = 0; e4 < 25; e4++) {
            float4 hv = *(const float4*)(hp + e4 * 4);
            float4 qv = *(const float4*)(qp + e4 * 4);
            d += hv.x * qv.x + hv.y * qv.y + hv.z * qv.z + hv.w * qv.w;
        }
        sGp[tid] = d;
    }
    __syncthreads();
    if (tid < NB) {
        const float* lp = sGp + tid * N_;
        float m = lp[0];
        for (int n = 1; n < N_; n++) m = fmaxf(m, lp[n]);
        float s = 0.f;
        float* pp = sG + tid * N_;
        for (int n = 0; n < N_; n++) { float ev = expf(lp[n] - m); pp[n] = ev; s += ev; }
        float inv = 1.f / s;
        for (int n = 0; n < N_; n++) pp[n] *= inv;
    }
    __syncthreads();
    {
        float* sU = sS + NB * SST;
        for (int i = tid; i < NB * E_; i += NTH) {
            int bi = i / E_, e_ = i % E_;
            float u = 0.f;
#pragma unroll
            for (int n = 0; n < N_; n++) u += sG[bi * N_ + n] * sH[(bi * N_ + n) * HST + e_];
            sU[bi * SST + e_] = u;
        }
    }
    __syncthreads();
    {
        const float* sQ = sS;
        const float* sU = sS + NB * SST;
        float ao = *a_out_p;
        for (int i = tid; i < NB * E_; i += NTH) {
            int bi = i / E_, f_ = i % E_;
            float acc = sQ[bi * SST + f_] + H_b[f_];
            const float* hw = sW + f_ * E_;
            const float* up = sU + bi * SST;
            for (int e4 = 0; e4 < 25; e4++) {
                float4 hv = *(const float4*)(hw + e4 * 4);
                float4 uv = *(const float4*)(up + e4 * 4);
                acc += hv.x * uv.x + hv.y * uv.y + hv.z * uv.z + hv.w * uv.w;
            }
            g_ya[(long)(b0g + bi) * E_ + f_] = (acc >= 0.f) ? acc : ao * acc;
        }
    }
}

// ============================================================
// K3: convert R_w and g_ya into packed bf16 hi/lo pair rows
// ============================================================
__global__ void convert_kernel(const float* __restrict__ R_w) {
    int idx = blockIdx.x * 256 + threadIdx.x;
    const int RTOT = V_ * 60;
    if (idx < RTOT) {
        int v = idx / 60, p = idx % 60;
        uint32_t hi = 0, lo = 0;
        if (p < 50) {
            float2 rv = *(const float2*)(R_w + (long)v * E_ + 2 * p);
            split2(rv.x, rv.y, hi, lo);
        }
        g_Rhi[idx] = hi;
        g_Rlo[idx] = lo;
    } else if (idx < RTOT + B_ * 60) {
        int i = idx - RTOT;
        int b = i / 60, p = i % 60;
        uint32_t hi = 0, lo = 0;
        if (p < 50) {
            float2 yv = *(const float2*)(g_ya + (long)b * E_ + 2 * p);
            split2(yv.x, yv.y, hi, lo);
        }
        g_Yhi[i] = hi;
        g_Ylo[i] = lo;
    }
}

// ============================================================
// K4: out = ya @ R_w^T + R_b on HMMA (bf16x3). 128b x 128v tiles.
// ============================================================
#define O_AHI 0
#define O_ALO 30720
#define O_BHI 61440
#define O_BLO 92160
#define OUT_SMEM 122880

__global__ __launch_bounds__(256, 1) void out_mma_kernel(
    const float* __restrict__ R_b, float* __restrict__ out)
{
    extern __shared__ char smo[];
    const int tid = threadIdx.x;
    const int w = tid >> 5;
    const int lane = tid & 31;
    const int v0 = blockIdx.x * 128;
    const int b0 = blockIdx.y * 128;
    const uint32_t smb = smem_u32(smo);

    uint32_t* sAhi = (uint32_t*)(smo + O_AHI);
    uint32_t* sAlo = (uint32_t*)(smo + O_ALO);
    uint32_t* sBhi = (uint32_t*)(smo + O_BHI);
    uint32_t* sBlo = (uint32_t*)(smo + O_BLO);
    for (int i = tid; i < 128 * 60; i += 256) {
        int r = i / 60, p = i % 60;
        sAhi[i] = g_Yhi[(b0 + r) * 60 + p];
        sAlo[i] = g_Ylo[(b0 + r) * 60 + p];
        sBhi[i] = g_Rhi[(long)(v0 + r) * 60 + p];
        sBlo[i] = g_Rlo[(long)(v0 + r) * 60 + p];
    }
    __syncthreads();

    const int mw = w >> 1, nw = w & 1;
    const int m0 = mw * 32;
    const int n0 = nw * 64;
    const int qr = lane >> 2, qc = lane & 3;
    const int grp = lane >> 3, lr = lane & 7;

    float acc[2][8][4];
#pragma unroll
    for (int mh = 0; mh < 2; mh++)
#pragma unroll
        for (int j = 0; j < 8; j++)
#pragma unroll
            for (int q = 0; q < 4; q++) acc[mh][j][q] = 0.f;

#pragma unroll
    for (int k = 0; k < 7; k++) {
        uint32_t ah[2][4], al[2][4];
#pragma unroll
        for (int mh = 0; mh < 2; mh++) {
            uint32_t aaddr = smb + O_AHI + (uint32_t)((m0 + 16 * mh + lr + ((grp & 1) << 3)) * 240
                           + k * 32 + ((grp >> 1) << 4));
            ldsm4(ah[mh], aaddr);
            ldsm4(al[mh], aaddr + 30720u);
        }
#pragma unroll
        for (int pq = 0; pq < 4; pq++) {
            uint32_t addr = smb + O_BHI + (uint32_t)((n0 + pq * 16 + lr + (grp >> 1) * 8) * 240
                          + k * 32 + (grp & 1) * 16);
            uint32_t bh[4], bl[4];
            ldsm4(bh, addr);
            ldsm4(bl, addr + 30720u);
#pragma unroll
            for (int mh = 0; mh < 2; mh++)
#pragma unroll
                for (int jj = 0; jj < 2; jj++) {
                    int j = pq * 2 + jj;
                    mma16816(acc[mh][j], ah[mh], &bh[2 * jj]);
                    mma16816(acc[mh][j], al[mh], &bh[2 * jj]);
                    mma16816(acc[mh][j], ah[mh], &bl[2 * jj]);
                }
        }
    }

#pragma unroll
    for (int mh = 0; mh < 2; mh++) {
        int ra = b0 + m0 + 16 * mh + qr;
        int rb2 = ra + 8;
#pragma unroll
        for (int j = 0; j < 8; j++) {
            int c = v0 + n0 + j * 8 + 2 * qc;
            float2 rb = *(const float2*)(R_b + c);
            float2 o0 = make_float2(acc[mh][j][0] + rb.x, acc[mh][j][1] + rb.y);
            float2 o1 = make_float2(acc[mh][j][2] + rb.x, acc[mh][j][3] + rb.y);
            *(float2*)(out + (long)ra * V_ + c) = o0;
            *(float2*)(out + (long)rb2 * V_ + c) = o1;
        }
    }
}

// ============================================================
extern "C" void kernel_launch(void* const* d_in, const int* in_sizes, int n_in,
                              void* d_out, int out_size) {
    const float* in_data = (const float*)d_in[0];
    const float* f       = (const float*)d_in[1];
    const float* h0      = (const float*)d_in[2];
    const float* w_mem   = (const float*)d_in[3];
    const float* U_w     = (const float*)d_in[4];
    const float* V_w     = (const float*)d_in[5];
    const float* W_w     = (const float*)d_in[6];
    const float* a_dm    = (const float*)d_in[7];
    const float* H_w     = (const float*)d_in[8];
    const float* H_b     = (const float*)d_in[9];
    const float* R_w     = (const float*)d_in[10];
    const float* R_b     = (const float*)d_in[11];
    const float* a_out   = (const float*)d_in[12];
    float* out = (float*)d_out;

    cudaFuncSetAttribute(scan_mma_kernel, cudaFuncAttributeMaxDynamicSharedMemorySize,
                         SCAN_SMEM);
    cudaFuncSetAttribute(out_mma_kernel, cudaFuncAttributeMaxDynamicSharedMemorySize,
                         OUT_SMEM);

    scan_mma_kernel<<<B_ / NB, NTH, SCAN_SMEM>>>(U_w, V_w, W_w, w_mem, h0, a_dm,
                                                 in_data, f, H_w, H_b, a_out);
    const int conv_total = V_ * 60 + B_ * 60;
    convert_kernel<<<(conv_total + 255) / 256, 256>>>(R_w);
    dim3 g4(V_ / 128, B_ / 128);
    out_mma_kernel<<<g4, 256, OUT_SMEM>>>(R_b, out);
}